// round 2
// baseline (speedup 1.0000x reference)
#include <cuda_runtime.h>
#include <math.h>

#define T_STEPS 512
#define B_SZ    64
#define DIN     1024
#define DH      1024
#define TBROWS  (T_STEPS * B_SZ)   // 32768

#define NBLK 128
#define NTHR 256
#define CPB  8                      // output columns per block (per gate)
#define HS_STRIDE 66                // padded row stride of staged h tile
#define WS_FLOATS (3 * 1024 * CPB)          // 24576 floats = 96 KB
#define HS_FLOATS (256 * HS_STRIDE)         // 16896 floats = 66 KB
#define SMEM_BYTES ((WS_FLOATS + HS_FLOATS) * 4)

// ---------------- device scratch (static; no allocation allowed) -------------
__device__ float g_X[3ull * TBROWS * DH];   // x@Wih^T + b, per gate
__device__ float g_h [B_SZ * DH];
__device__ float g_u [B_SZ * DH];
__device__ float g_rh[B_SZ * DH];
__device__ unsigned g_bar_count;
__device__ volatile unsigned g_bar_gen;

// ============================================================================
// Software grid barrier (monotonic count; state reset by init kernel per run)
// ============================================================================
__device__ __forceinline__ void grid_barrier(unsigned& lgen) {
    __syncthreads();
    if (threadIdx.x == 0) {
        unsigned target = ++lgen;
        __threadfence();
        unsigned arr = atomicAdd(&g_bar_count, 1u) + 1u;
        if (arr == target * NBLK) {
            __threadfence();
            g_bar_gen = target;
        } else {
            while (g_bar_gen < target) { }
        }
        __threadfence();
    }
    __syncthreads();
}

// ============================================================================
// Phase 1: X[g] = emb @ w_ih_g^T + b_g  (128x128 tile fp32 SGEMM, NT)
// ============================================================================
__global__ __launch_bounds__(256, 2)
void gemm_input(const float* __restrict__ A,
                const float* __restrict__ Wu, const float* __restrict__ Wr,
                const float* __restrict__ Wc,
                const float* __restrict__ bu, const float* __restrict__ br,
                const float* __restrict__ bc) {
    const int g = blockIdx.z;
    const float* W    = (g == 0) ? Wu : (g == 1) ? Wr : Wc;
    const float* bias = (g == 0) ? bu : (g == 1) ? br : bc;
    float* X = g_X + (size_t)g * TBROWS * DH;

    __shared__ __align__(16) float As[8][128];
    __shared__ __align__(16) float Bs[8][128];

    const int tid = threadIdx.x;
    const int m0 = blockIdx.y * 128;
    const int n0 = blockIdx.x * 128;
    const int ty = tid >> 4;
    const int tx = tid & 15;
    const int lr = tid >> 1;
    const int lc = (tid & 1) * 4;

    float acc[8][8];
#pragma unroll
    for (int i = 0; i < 8; i++)
#pragma unroll
        for (int j = 0; j < 8; j++) acc[i][j] = 0.f;

    const float* Aptr = A + (size_t)(m0 + lr) * DIN + lc;
    const float* Wptr = W + (size_t)(n0 + lr) * DIN + lc;

    for (int k0 = 0; k0 < DIN; k0 += 8) {
        float4 av = *(const float4*)(Aptr + k0);
        float4 bv = *(const float4*)(Wptr + k0);
        As[lc + 0][lr] = av.x; As[lc + 1][lr] = av.y;
        As[lc + 2][lr] = av.z; As[lc + 3][lr] = av.w;
        Bs[lc + 0][lr] = bv.x; Bs[lc + 1][lr] = bv.y;
        Bs[lc + 2][lr] = bv.z; Bs[lc + 3][lr] = bv.w;
        __syncthreads();
#pragma unroll
        for (int k = 0; k < 8; k++) {
            float a[8], b[8];
            *(float4*)(a)     = *(const float4*)&As[k][ty * 8];
            *(float4*)(a + 4) = *(const float4*)&As[k][ty * 8 + 4];
            *(float4*)(b)     = *(const float4*)&Bs[k][tx * 8];
            *(float4*)(b + 4) = *(const float4*)&Bs[k][tx * 8 + 4];
#pragma unroll
            for (int i = 0; i < 8; i++)
#pragma unroll
                for (int j = 0; j < 8; j++) acc[i][j] += a[i] * b[j];
        }
        __syncthreads();
    }

    float bvals[8];
    *(float4*)(bvals)     = *(const float4*)(bias + n0 + tx * 8);
    *(float4*)(bvals + 4) = *(const float4*)(bias + n0 + tx * 8 + 4);
#pragma unroll
    for (int i = 0; i < 8; i++) {
        size_t row = (size_t)(m0 + ty * 8 + i) * DH + n0 + tx * 8;
        float4 o0 = make_float4(acc[i][0] + bvals[0], acc[i][1] + bvals[1],
                                acc[i][2] + bvals[2], acc[i][3] + bvals[3]);
        float4 o1 = make_float4(acc[i][4] + bvals[4], acc[i][5] + bvals[5],
                                acc[i][6] + bvals[6], acc[i][7] + bvals[7]);
        *(float4*)(X + row)     = o0;
        *(float4*)(X + row + 4) = o1;
    }
}

// ============================================================================
// init: h <- hx, reset barrier state (runs before persistent kernel each replay)
// ============================================================================
__global__ void init_h(const float* __restrict__ hx) {
    int i = blockIdx.x * 256 + threadIdx.x;
    g_h[i] = hx[i];
    if (i == 0) { g_bar_count = 0u; g_bar_gen = 0u; }
}

// ============================================================================
// Stage 256 k-rows of a [64 x 1024] matrix into hs[k][HS_STRIDE] (transposed).
// s in [0,128) comes from column window k0_lo, s in [128,256) from k0_hi.
// Conflict-free STS: bank = (8*(tid&3) + (tid>>2)%32 ...) covers all 32 banks.
// ============================================================================
__device__ __forceinline__ void stage_tile(float* hs, const float* __restrict__ src,
                                           int k0_lo, int k0_hi) {
    const int m  = threadIdx.x >> 2;
    const int kb = (threadIdx.x & 3) * 4;
#pragma unroll
    for (int it = 0; it < 16; it++) {
        int s = kb + 16 * it;
        int gk = (it < 8) ? (k0_lo + s) : (k0_hi + s - 128);
        float4 v = *(const float4*)(src + m * DH + gk);
        hs[(s + 0) * HS_STRIDE + m] = v.x;
        hs[(s + 1) * HS_STRIDE + m] = v.y;
        hs[(s + 2) * HS_STRIDE + m] = v.z;
        hs[(s + 3) * HS_STRIDE + m] = v.w;
    }
}

// ============================================================================
// Persistent recurrence kernel. 128 CTAs, each owns CPB=8 output columns of
// all three W_hh matrices (kept in SMEM for all 512 steps).
// Per step:  phase A -> u = sigmoid(Xu + h Wu^T), rh = sigmoid(Xr + h Wr^T)*h
//            [grid barrier]
//            phase B -> c = tanh(Xc + rh Wc^T); h = (1-u)h + u c ; write out
//            [grid barrier]
// ============================================================================
__global__ __launch_bounds__(NTHR, 1)
void gru_persistent(const float* __restrict__ Wu, const float* __restrict__ Wr,
                    const float* __restrict__ Wc, float* __restrict__ out,
                    int write_tail) {
    extern __shared__ float smem[];
    float* ws = smem;              // [3][1024][CPB]
    float* hs = smem + WS_FLOATS;  // [256][HS_STRIDE]

    const int tid = threadIdx.x;
    const int n0 = blockIdx.x * CPB;

    // ---- load persistent weight slice: ws[(g*1024 + k)*8 + c]
    for (int g = 0; g < 3; g++) {
        const float* W = (g == 0) ? Wu : (g == 1) ? Wr : Wc;
#pragma unroll
        for (int c = 0; c < CPB; c++) {
            float4 v = *(const float4*)(W + (size_t)(n0 + c) * DH + tid * 4);
            int kb = tid * 4;
            ws[(g * 1024 + kb + 0) * 8 + c] = v.x;
            ws[(g * 1024 + kb + 1) * 8 + c] = v.y;
            ws[(g * 1024 + kb + 2) * 8 + c] = v.z;
            ws[(g * 1024 + kb + 3) * 8 + c] = v.w;
        }
    }
    __syncthreads();

    // phase A roles: 32 row-pairs x 8 (gate, colpair) groups
    const int mpA = tid & 31;
    const int pA  = tid >> 5;
    const int gA  = pA >> 2;          // 0 = update, 1 = reset
    const int cA  = (pA & 3) * 2;     // 0,2,4,6

    // phase B roles: k-split halves, 32 row-pairs x 4 colpairs each
    const int half = tid >> 7;
    const int tid2 = tid & 127;
    const int mpB  = tid2 & 31;
    const int cB   = (tid2 >> 5) * 2;

    unsigned lgen = 0;

    for (int t = 0; t < T_STEPS; t++) {
        // ================= phase A =================
        float a00 = 0.f, a01 = 0.f, a10 = 0.f, a11 = 0.f;
        for (int kc = 0; kc < DH; kc += 256) {
            stage_tile(hs, g_h, kc, kc + 128);   // contiguous 256 window
            __syncthreads();
            const float* wp = ws + ((size_t)gA * 1024 + kc) * 8 + cA;
            const float* hp = hs + mpA * 2;
#pragma unroll 8
            for (int k = 0; k < 256; k++) {
                float2 av = *(const float2*)(hp + k * HS_STRIDE);
                float2 bv = *(const float2*)(wp + k * 8);
                a00 += av.x * bv.x; a01 += av.x * bv.y;
                a10 += av.y * bv.x; a11 += av.y * bv.y;
            }
            __syncthreads();
        }
        {
            const float* Xg = g_X + ((size_t)gA * TBROWS + (size_t)t * B_SZ) * DH;
            int r0 = mpA * 2, n = n0 + cA;
            float p00 = a00 + Xg[r0 * DH + n];
            float p01 = a01 + Xg[r0 * DH + n + 1];
            float p10 = a10 + Xg[(r0 + 1) * DH + n];
            float p11 = a11 + Xg[(r0 + 1) * DH + n + 1];
            float s00 = 1.f / (1.f + expf(-p00));
            float s01 = 1.f / (1.f + expf(-p01));
            float s10 = 1.f / (1.f + expf(-p10));
            float s11 = 1.f / (1.f + expf(-p11));
            if (gA == 0) {
                g_u[r0 * DH + n]       = s00; g_u[r0 * DH + n + 1]       = s01;
                g_u[(r0 + 1) * DH + n] = s10; g_u[(r0 + 1) * DH + n + 1] = s11;
            } else {
                g_rh[r0 * DH + n]       = s00 * g_h[r0 * DH + n];
                g_rh[r0 * DH + n + 1]   = s01 * g_h[r0 * DH + n + 1];
                g_rh[(r0+1) * DH + n]   = s10 * g_h[(r0 + 1) * DH + n];
                g_rh[(r0+1) * DH + n+1] = s11 * g_h[(r0 + 1) * DH + n + 1];
            }
        }
        grid_barrier(lgen);

        // ================= phase B (k-split) =================
        float b00 = 0.f, b01 = 0.f, b10 = 0.f, b11 = 0.f;
        for (int kc = 0; kc < 512; kc += 128) {
            stage_tile(hs, g_rh, kc, 512 + kc);  // lower half rows 0..127, upper 128..255
            __syncthreads();
            const float* wp = ws + (size_t)(2 * 1024 + half * 512 + kc) * 8 + cB;
            const float* hp = hs + half * 128 * HS_STRIDE + mpB * 2;
#pragma unroll 8
            for (int k = 0; k < 128; k++) {
                float2 av = *(const float2*)(hp + k * HS_STRIDE);
                float2 bv = *(const float2*)(wp + k * 8);
                b00 += av.x * bv.x; b01 += av.x * bv.y;
                b10 += av.y * bv.x; b11 += av.y * bv.y;
            }
            __syncthreads();
        }
        // combine halves via smem (reuse hs scratch)
        if (half == 1) {
            ((float4*)hs)[tid2] = make_float4(b00, b01, b10, b11);
        }
        __syncthreads();
        if (half == 0) {
            float4 o = ((float4*)hs)[tid2];
            b00 += o.x; b01 += o.y; b10 += o.z; b11 += o.w;
            const float* Xc = g_X + (2ull * TBROWS + (size_t)t * B_SZ) * DH;
            int r0 = mpB * 2, n = n0 + cB;
#pragma unroll
            for (int i = 0; i < 2; i++) {
                int m = r0 + i;
                float pc0 = ((i == 0) ? b00 : b10) + Xc[m * DH + n];
                float pc1 = ((i == 0) ? b01 : b11) + Xc[m * DH + n + 1];
                float c0 = tanhf(pc0), c1 = tanhf(pc1);
                float u0 = g_u[m * DH + n], u1 = g_u[m * DH + n + 1];
                float h0 = g_h[m * DH + n], h1 = g_h[m * DH + n + 1];
                float hn0 = (1.f - u0) * h0 + u0 * c0;
                float hn1 = (1.f - u1) * h1 + u1 * c1;
                g_h[m * DH + n]     = hn0;
                g_h[m * DH + n + 1] = hn1;
                size_t ob = ((size_t)t * B_SZ + m) * DH + n;
                out[ob] = hn0; out[ob + 1] = hn1;
                if (write_tail && t == T_STEPS - 1) {
                    size_t tb = ((size_t)T_STEPS * B_SZ + m) * DH + n;
                    out[tb] = hn0; out[tb + 1] = hn1;
                }
            }
        }
        grid_barrier(lgen);
    }
}

// ============================================================================
// Launch: 3 graph nodes total (keeps graph upload allocation at zero).
// ============================================================================
extern "C" void kernel_launch(void* const* d_in, const int* in_sizes, int n_in,
                              void* d_out, int out_size) {
    const float* emb    = (const float*)d_in[0];
    const float* hx     = (const float*)d_in[1];
    const float* w_ih_u = (const float*)d_in[2];
    const float* w_ih_r = (const float*)d_in[3];
    const float* w_ih_c = (const float*)d_in[4];
    const float* w_hh_u = (const float*)d_in[5];
    const float* w_hh_r = (const float*)d_in[6];
    const float* w_hh_c = (const float*)d_in[7];
    const float* b_u    = (const float*)d_in[8];
    const float* b_r    = (const float*)d_in[9];
    const float* b_c    = (const float*)d_in[10];
    float* out = (float*)d_out;

    const long long main_elems = (long long)T_STEPS * B_SZ * DH;
    int write_tail = ((long long)out_size >= main_elems + (long long)B_SZ * DH) ? 1 : 0;

    cudaFuncSetAttribute(gru_persistent,
                         cudaFuncAttributeMaxDynamicSharedMemorySize, SMEM_BYTES);

    dim3 g1(DH / 128, TBROWS / 128, 3);
    gemm_input<<<g1, 256>>>(emb, w_ih_u, w_ih_r, w_ih_c, b_u, b_r, b_c);
    init_h<<<(B_SZ * DH) / 256, 256>>>(hx);
    gru_persistent<<<NBLK, NTHR, SMEM_BYTES>>>(w_hh_u, w_hh_r, w_hh_c, out, write_tail);
}

// round 4
// speedup vs baseline: 1.0961x; 1.0961x over previous
#include <cuda_runtime.h>
#include <cuda_bf16.h>
#include <math.h>
#include <stdint.h>

#define T_STEPS 512
#define B_SZ    64
#define DIN     1024
#define DH      1024
#define TBROWS  (T_STEPS * B_SZ)   // 32768

#define NBLK 128
#define NTHR 256
#define CPB  8
#define HS_STRIDE 66
#define WS_FLOATS (3 * 1024 * CPB)
#define HS_FLOATS (256 * HS_STRIDE)
#define SMEM_BYTES ((WS_FLOATS + HS_FLOATS) * 4)

// ---------------- device scratch (static; no allocation allowed) -------------
__device__ float g_X[3ull * TBROWS * DH];            // x@Wih^T + b, per gate
__device__ __nv_bfloat16 g_Ah[(size_t)TBROWS * DIN]; // emb split hi
__device__ __nv_bfloat16 g_Al[(size_t)TBROWS * DIN]; // emb split lo
__device__ __nv_bfloat16 g_Bh[3ull * DH * DIN];      // w_ih split hi (3 gates)
__device__ __nv_bfloat16 g_Bl[3ull * DH * DIN];      // w_ih split lo
__device__ float g_h [B_SZ * DH];
__device__ float g_u [B_SZ * DH];
__device__ float g_rh[B_SZ * DH];
__device__ unsigned g_bar_count;
__device__ volatile unsigned g_bar_gen;

// ============================================================================
// helpers
// ============================================================================
__device__ __forceinline__ uint32_t smem_to_u32(const void* p) {
    uint32_t a;
    asm("{ .reg .u64 t; cvta.to.shared.u64 t, %1; cvt.u32.u64 %0, t; }"
        : "=r"(a) : "l"(p));
    return a;
}
__device__ __forceinline__ void cp16(uint32_t dst, const void* src) {
    asm volatile("cp.async.cg.shared.global [%0], [%1], 16;"
                 :: "r"(dst), "l"(src));
}
#define CP_COMMIT() asm volatile("cp.async.commit_group;" ::: "memory")
#define CP_WAIT(n)  asm volatile("cp.async.wait_group %0;" :: "n"(n) : "memory")

#define LDSM_X4(r0, r1, r2, r3, addr) \
    asm volatile("ldmatrix.sync.aligned.m8n8.x4.shared.b16 {%0,%1,%2,%3}, [%4];" \
                 : "=r"(r0), "=r"(r1), "=r"(r2), "=r"(r3) : "r"(addr))

#define MMA_BF16(d, a, b) \
    asm volatile("mma.sync.aligned.m16n8k16.row.col.f32.bf16.bf16.f32 " \
                 "{%0,%1,%2,%3}, {%4,%5,%6,%7}, {%8,%9}, {%0,%1,%2,%3};" \
                 : "+f"((d)[0]), "+f"((d)[1]), "+f"((d)[2]), "+f"((d)[3]) \
                 : "r"((a)[0]), "r"((a)[1]), "r"((a)[2]), "r"((a)[3]), \
                   "r"((b)[0]), "r"((b)[1]))

// ============================================================================
// split-convert: fp32 -> (bf16 hi, bf16 lo = bf16(x - float(hi)))
// ============================================================================
__global__ void conv_split(const float* __restrict__ src,
                           __nv_bfloat16* __restrict__ dh,
                           __nv_bfloat16* __restrict__ dl, int n4) {
    int i = blockIdx.x * 256 + threadIdx.x;
    if (i >= n4) return;
    float4 v = *(const float4*)(src + (size_t)i * 4);
    __nv_bfloat16 h0 = __float2bfloat16(v.x);
    __nv_bfloat16 h1 = __float2bfloat16(v.y);
    __nv_bfloat16 h2 = __float2bfloat16(v.z);
    __nv_bfloat16 h3 = __float2bfloat16(v.w);
    __nv_bfloat162 ph0, ph1, pl0, pl1;
    ph0.x = h0; ph0.y = h1; ph1.x = h2; ph1.y = h3;
    pl0.x = __float2bfloat16(v.x - __bfloat162float(h0));
    pl0.y = __float2bfloat16(v.y - __bfloat162float(h1));
    pl1.x = __float2bfloat16(v.z - __bfloat162float(h2));
    pl1.y = __float2bfloat16(v.w - __bfloat162float(h3));
    *(__nv_bfloat162*)(dh + (size_t)i * 4)     = ph0;
    *(__nv_bfloat162*)(dh + (size_t)i * 4 + 2) = ph1;
    *(__nv_bfloat162*)(dl + (size_t)i * 4)     = pl0;
    *(__nv_bfloat162*)(dl + (size_t)i * 4 + 2) = pl1;
}

// ============================================================================
// HMMA input GEMM: X[g] = emb @ w_ih_g^T + b_g (2-term bf16 split, fp32 acc)
// CTA 128x128, 8 warps (4m x 2n), warp tile 32x64, K-tile 32,
// 2-stage cp.async pipeline, ldmatrix.x4 frags, 80B smem row stride.
// ============================================================================
#define KT       32                 // K elements per tile
#define NKT      (DIN / KT)         // 32 tiles
#define TSTRB    80                 // bytes per smem row (32 bf16 + 16B pad)
#define TILE_SB  (128 * TSTRB)      // 10240 B per operand tile
#define STAGE_SB (4 * TILE_SB)      // Ah, Al, Bh, Bl
#define GEMM_SM  (2 * STAGE_SB)     // 81920 B

__global__ __launch_bounds__(256)
void gemm_input_tc(const float* __restrict__ bu, const float* __restrict__ br,
                   const float* __restrict__ bc) {
    extern __shared__ char smem[];
    const uint32_t sm0 = smem_to_u32(smem);

    const int g  = blockIdx.z;
    const int n0 = blockIdx.x * 128;
    const int m0 = blockIdx.y * 128;
    const float* bias = (g == 0) ? bu : (g == 1) ? br : bc;
    float* X = g_X + (size_t)g * TBROWS * DH;

    const int tid  = threadIdx.x;
    const int wid  = tid >> 5;
    const int lane = tid & 31;
    const int wm   = wid & 3;            // 0..3 -> m offset 32*wm
    const int wn   = wid >> 2;           // 0..1 -> n offset 64*wn

    // ---- staging roles: part p (Ah/Al/Bh/Bl), rows q and q+64, 4 chunks each
    const int p = tid >> 6;
    const int q = tid & 63;
    const __nv_bfloat16* srcb;
    if (p == 0)      srcb = g_Ah + (size_t)(m0 + q) * DIN;
    else if (p == 1) srcb = g_Al + (size_t)(m0 + q) * DIN;
    else if (p == 2) srcb = g_Bh + ((size_t)g * DH + n0 + q) * DIN;
    else             srcb = g_Bl + ((size_t)g * DH + n0 + q) * DIN;
    const uint32_t dstb = sm0 + p * TILE_SB + q * TSTRB;

    float acc[2][8][4];
#pragma unroll
    for (int mf = 0; mf < 2; mf++)
#pragma unroll
        for (int nf = 0; nf < 8; nf++)
#pragma unroll
            for (int e = 0; e < 4; e++) acc[mf][nf][e] = 0.f;

    // ---- issue stage 0
#pragma unroll
    for (int j = 0; j < 4; j++) {
        cp16(dstb + j * 16,               srcb + j * 8);
        cp16(dstb + 64 * TSTRB + j * 16,  srcb + (size_t)64 * DIN + j * 8);
    }
    CP_COMMIT();

    for (int c = 0; c < NKT; c++) {
        const uint32_t sb = sm0 + (c & 1) * STAGE_SB;
        if (c + 1 < NKT) {
            const uint32_t db = dstb ^ ((~c & 1) ? 0 : 0);  // placeholder
            const uint32_t d2 = sm0 + ((c + 1) & 1) * STAGE_SB
                              + p * TILE_SB + q * TSTRB;
            const __nv_bfloat16* s2 = srcb + (c + 1) * KT;
#pragma unroll
            for (int j = 0; j < 4; j++) {
                cp16(d2 + j * 16,              s2 + j * 8);
                cp16(d2 + 64 * TSTRB + j * 16, s2 + (size_t)64 * DIN + j * 8);
            }
            CP_COMMIT();
            CP_WAIT(1);
        } else {
            CP_WAIT(0);
        }
        __syncthreads();

        const uint32_t arow = (lane & 15);
        const uint32_t acol = (lane >> 4) * 16;
#pragma unroll
        for (int s = 0; s < 2; s++) {
            uint32_t ah[2][4], al[2][4], bh[8][2], bl[8][2];
#pragma unroll
            for (int mf = 0; mf < 2; mf++) {
                uint32_t ra = sb + (32 * wm + 16 * mf + arow) * TSTRB + acol + s * 32;
                LDSM_X4(ah[mf][0], ah[mf][1], ah[mf][2], ah[mf][3], ra);
                LDSM_X4(al[mf][0], al[mf][1], al[mf][2], al[mf][3], ra + TILE_SB);
            }
#pragma unroll
            for (int nfp = 0; nfp < 4; nfp++) {
                uint32_t rb = sb + 2 * TILE_SB
                            + (64 * wn + 16 * nfp + arow) * TSTRB + acol + s * 32;
                uint32_t r0, r1, r2, r3;
                LDSM_X4(r0, r1, r2, r3, rb);
                bh[2 * nfp][0] = r0; bh[2 * nfp][1] = r2;
                bh[2 * nfp + 1][0] = r1; bh[2 * nfp + 1][1] = r3;
                LDSM_X4(r0, r1, r2, r3, rb + TILE_SB);
                bl[2 * nfp][0] = r0; bl[2 * nfp][1] = r2;
                bl[2 * nfp + 1][0] = r1; bl[2 * nfp + 1][1] = r3;
            }
#pragma unroll
            for (int mf = 0; mf < 2; mf++)
#pragma unroll
                for (int nf = 0; nf < 8; nf++) {
                    MMA_BF16(acc[mf][nf], ah[mf], bh[nf]);
                    MMA_BF16(acc[mf][nf], ah[mf], bl[nf]);
                    MMA_BF16(acc[mf][nf], al[mf], bh[nf]);
                }
        }
        __syncthreads();
    }

    // ---- epilogue: add bias, write fp32
#pragma unroll
    for (int mf = 0; mf < 2; mf++) {
        int row0 = m0 + wm * 32 + mf * 16 + (lane >> 2);
#pragma unroll
        for (int nf = 0; nf < 8; nf++) {
            int col = n0 + wn * 64 + nf * 8 + (lane & 3) * 2;
            float2 bv = *(const float2*)(bias + col);
            float2 o0 = make_float2(acc[mf][nf][0] + bv.x, acc[mf][nf][1] + bv.y);
            float2 o1 = make_float2(acc[mf][nf][2] + bv.x, acc[mf][nf][3] + bv.y);
            *(float2*)(X + (size_t)row0 * DH + col)       = o0;
            *(float2*)(X + (size_t)(row0 + 8) * DH + col) = o1;
        }
    }
}

// ============================================================================
// Software grid barrier
// ============================================================================
__device__ __forceinline__ void grid_barrier(unsigned& lgen) {
    __syncthreads();
    if (threadIdx.x == 0) {
        unsigned target = ++lgen;
        __threadfence();
        unsigned arr = atomicAdd(&g_bar_count, 1u) + 1u;
        if (arr == target * NBLK) {
            __threadfence();
            g_bar_gen = target;
        } else {
            while (g_bar_gen < target) { }
        }
        __threadfence();
    }
    __syncthreads();
}

// ============================================================================
// init: h <- hx, reset barrier state
// ============================================================================
__global__ void init_h(const float* __restrict__ hx) {
    int i = blockIdx.x * 256 + threadIdx.x;
    g_h[i] = hx[i];
    if (i == 0) { g_bar_count = 0u; g_bar_gen = 0u; }
}

// ============================================================================
// Stage 256 k-rows of a [64 x 1024] matrix into hs[k][HS_STRIDE] (transposed).
// ============================================================================
__device__ __forceinline__ void stage_tile(float* hs, const float* __restrict__ src,
                                           int k0_lo, int k0_hi) {
    const int m  = threadIdx.x >> 2;
    const int kb = (threadIdx.x & 3) * 4;
#pragma unroll
    for (int it = 0; it < 16; it++) {
        int s = kb + 16 * it;
        int gk = (it < 8) ? (k0_lo + s) : (k0_hi + s - 128);
        float4 v = *(const float4*)(src + m * DH + gk);
        hs[(s + 0) * HS_STRIDE + m] = v.x;
        hs[(s + 1) * HS_STRIDE + m] = v.y;
        hs[(s + 2) * HS_STRIDE + m] = v.z;
        hs[(s + 3) * HS_STRIDE + m] = v.w;
    }
}

// ============================================================================
// Persistent recurrence kernel (unchanged from passing round 2 version)
// ============================================================================
__global__ __launch_bounds__(NTHR, 1)
void gru_persistent(const float* __restrict__ Wu, const float* __restrict__ Wr,
                    const float* __restrict__ Wc, float* __restrict__ out,
                    int write_tail) {
    extern __shared__ float smemf[];
    float* ws = smemf;
    float* hs = smemf + WS_FLOATS;

    const int tid = threadIdx.x;
    const int n0 = blockIdx.x * CPB;

    for (int g = 0; g < 3; g++) {
        const float* W = (g == 0) ? Wu : (g == 1) ? Wr : Wc;
#pragma unroll
        for (int c = 0; c < CPB; c++) {
            float4 v = *(const float4*)(W + (size_t)(n0 + c) * DH + tid * 4);
            int kb = tid * 4;
            ws[(g * 1024 + kb + 0) * 8 + c] = v.x;
            ws[(g * 1024 + kb + 1) * 8 + c] = v.y;
            ws[(g * 1024 + kb + 2) * 8 + c] = v.z;
            ws[(g * 1024 + kb + 3) * 8 + c] = v.w;
        }
    }
    __syncthreads();

    const int mpA = tid & 31;
    const int pA  = tid >> 5;
    const int gA  = pA >> 2;
    const int cA  = (pA & 3) * 2;

    const int half = tid >> 7;
    const int tid2 = tid & 127;
    const int mpB  = tid2 & 31;
    const int cB   = (tid2 >> 5) * 2;

    unsigned lgen = 0;

    for (int t = 0; t < T_STEPS; t++) {
        float a00 = 0.f, a01 = 0.f, a10 = 0.f, a11 = 0.f;
        for (int kc = 0; kc < DH; kc += 256) {
            stage_tile(hs, g_h, kc, kc + 128);
            __syncthreads();
            const float* wp = ws + ((size_t)gA * 1024 + kc) * 8 + cA;
            const float* hp = hs + mpA * 2;
#pragma unroll 8
            for (int k = 0; k < 256; k++) {
                float2 av = *(const float2*)(hp + k * HS_STRIDE);
                float2 bv = *(const float2*)(wp + k * 8);
                a00 += av.x * bv.x; a01 += av.x * bv.y;
                a10 += av.y * bv.x; a11 += av.y * bv.y;
            }
            __syncthreads();
        }
        {
            const float* Xg = g_X + ((size_t)gA * TBROWS + (size_t)t * B_SZ) * DH;
            int r0 = mpA * 2, n = n0 + cA;
            float p00 = a00 + Xg[r0 * DH + n];
            float p01 = a01 + Xg[r0 * DH + n + 1];
            float p10 = a10 + Xg[(r0 + 1) * DH + n];
            float p11 = a11 + Xg[(r0 + 1) * DH + n + 1];
            float s00 = 1.f / (1.f + expf(-p00));
            float s01 = 1.f / (1.f + expf(-p01));
            float s10 = 1.f / (1.f + expf(-p10));
            float s11 = 1.f / (1.f + expf(-p11));
            if (gA == 0) {
                g_u[r0 * DH + n]       = s00; g_u[r0 * DH + n + 1]       = s01;
                g_u[(r0 + 1) * DH + n] = s10; g_u[(r0 + 1) * DH + n + 1] = s11;
            } else {
                g_rh[r0 * DH + n]       = s00 * g_h[r0 * DH + n];
                g_rh[r0 * DH + n + 1]   = s01 * g_h[r0 * DH + n + 1];
                g_rh[(r0+1) * DH + n]   = s10 * g_h[(r0 + 1) * DH + n];
                g_rh[(r0+1) * DH + n+1] = s11 * g_h[(r0 + 1) * DH + n + 1];
            }
        }
        grid_barrier(lgen);

        float b00 = 0.f, b01 = 0.f, b10 = 0.f, b11 = 0.f;
        for (int kc = 0; kc < 512; kc += 128) {
            stage_tile(hs, g_rh, kc, 512 + kc);
            __syncthreads();
            const float* wp = ws + (size_t)(2 * 1024 + half * 512 + kc) * 8 + cB;
            const float* hp = hs + half * 128 * HS_STRIDE + mpB * 2;
#pragma unroll 8
            for (int k = 0; k < 128; k++) {
                float2 av = *(const float2*)(hp + k * HS_STRIDE);
                float2 bv = *(const float2*)(wp + k * 8);
                b00 += av.x * bv.x; b01 += av.x * bv.y;
                b10 += av.y * bv.x; b11 += av.y * bv.y;
            }
            __syncthreads();
        }
        if (half == 1) {
            ((float4*)hs)[tid2] = make_float4(b00, b01, b10, b11);
        }
        __syncthreads();
        if (half == 0) {
            float4 o = ((float4*)hs)[tid2];
            b00 += o.x; b01 += o.y; b10 += o.z; b11 += o.w;
            const float* Xc = g_X + (2ull * TBROWS + (size_t)t * B_SZ) * DH;
            int r0 = mpB * 2, n = n0 + cB;
#pragma unroll
            for (int i = 0; i < 2; i++) {
                int m = r0 + i;
                float pc0 = ((i == 0) ? b00 : b10) + Xc[m * DH + n];
                float pc1 = ((i == 0) ? b01 : b11) + Xc[m * DH + n + 1];
                float c0 = tanhf(pc0), c1 = tanhf(pc1);
                float u0 = g_u[m * DH + n], u1 = g_u[m * DH + n + 1];
                float h0 = g_h[m * DH + n], h1 = g_h[m * DH + n + 1];
                float hn0 = (1.f - u0) * h0 + u0 * c0;
                float hn1 = (1.f - u1) * h1 + u1 * c1;
                g_h[m * DH + n]     = hn0;
                g_h[m * DH + n + 1] = hn1;
                size_t ob = ((size_t)t * B_SZ + m) * DH + n;
                out[ob] = hn0; out[ob + 1] = hn1;
                if (write_tail && t == T_STEPS - 1) {
                    size_t tb = ((size_t)T_STEPS * B_SZ + m) * DH + n;
                    out[tb] = hn0; out[tb + 1] = hn1;
                }
            }
        }
        grid_barrier(lgen);
    }
}

// ============================================================================
// Launch: few graph nodes (conversions + gemm + init + persistent)
// ============================================================================
extern "C" void kernel_launch(void* const* d_in, const int* in_sizes, int n_in,
                              void* d_out, int out_size) {
    const float* emb    = (const float*)d_in[0];
    const float* hx     = (const float*)d_in[1];
    const float* w_ih_u = (const float*)d_in[2];
    const float* w_ih_r = (const float*)d_in[3];
    const float* w_ih_c = (const float*)d_in[4];
    const float* w_hh_u = (const float*)d_in[5];
    const float* w_hh_r = (const float*)d_in[6];
    const float* w_hh_c = (const float*)d_in[7];
    const float* b_u    = (const float*)d_in[8];
    const float* b_r    = (const float*)d_in[9];
    const float* b_c    = (const float*)d_in[10];
    float* out = (float*)d_out;

    const long long main_elems = (long long)T_STEPS * B_SZ * DH;
    int write_tail = ((long long)out_size >= main_elems + (long long)B_SZ * DH) ? 1 : 0;

    cudaFuncSetAttribute(gru_persistent,
                         cudaFuncAttributeMaxDynamicSharedMemorySize, SMEM_BYTES);
    cudaFuncSetAttribute(gemm_input_tc,
                         cudaFuncAttributeMaxDynamicSharedMemorySize, GEMM_SM);

    // resolve device-symbol addresses (host side, outside capture-sensitive ops)
    __nv_bfloat16 *pAh, *pAl, *pBh, *pBl;
    cudaGetSymbolAddress((void**)&pAh, g_Ah);
    cudaGetSymbolAddress((void**)&pAl, g_Al);
    cudaGetSymbolAddress((void**)&pBh, g_Bh);
    cudaGetSymbolAddress((void**)&pBl, g_Bl);

    // split-convert emb and the three input weight matrices
    {
        int n4 = TBROWS * DIN / 4;
        conv_split<<<(n4 + 255) / 256, 256>>>(emb, pAh, pAl, n4);
        int w4 = DH * DIN / 4;
        conv_split<<<(w4 + 255) / 256, 256>>>(w_ih_u, pBh,                 pBl,                 w4);
        conv_split<<<(w4 + 255) / 256, 256>>>(w_ih_r, pBh + (size_t)DH*DIN,   pBl + (size_t)DH*DIN,   w4);
        conv_split<<<(w4 + 255) / 256, 256>>>(w_ih_c, pBh + 2ull*DH*DIN,      pBl + 2ull*DH*DIN,      w4);
    }

    dim3 g1(DH / 128, TBROWS / 128, 3);
    gemm_input_tc<<<g1, 256, GEMM_SM>>>(b_u, b_r, b_c);
    init_h<<<(B_SZ * DH) / 256, 256>>>(hx);
    gru_persistent<<<NBLK, NTHR, SMEM_BYTES>>>(w_hh_u, w_hh_r, w_hh_c, out, write_tail);
}

// round 6
// speedup vs baseline: 1.3953x; 1.2730x over previous
#include <cuda_runtime.h>
#include <cuda_bf16.h>
#include <math.h>
#include <stdint.h>

#define T_STEPS 512
#define B_SZ    64
#define DIN     1024
#define DH      1024
#define TBROWS  (T_STEPS * B_SZ)   // 32768

#define NBLK 128
#define NTHR 256

// ---------------- device scratch (static; no allocation allowed) -------------
__device__ float g_X[3ull * TBROWS * DH];            // x@Wih^T + b, per gate
__device__ __nv_bfloat16 g_Ah[(size_t)TBROWS * DIN]; // emb split hi
__device__ __nv_bfloat16 g_Al[(size_t)TBROWS * DIN]; // emb split lo
__device__ __nv_bfloat16 g_Bh[3ull * DH * DIN];      // w_ih split hi (3 gates)
__device__ __nv_bfloat16 g_Bl[3ull * DH * DIN];      // w_ih split lo
__device__ float g_h [B_SZ * DH];                    // hidden state fp32
__device__ float g_u [B_SZ * DH];                    // update gate
__device__ __nv_bfloat16 g_hh [B_SZ * DH];           // h split hi
__device__ __nv_bfloat16 g_hl [B_SZ * DH];           // h split lo
__device__ __nv_bfloat16 g_rhh[B_SZ * DH];           // (r*h) split hi
__device__ __nv_bfloat16 g_rhl[B_SZ * DH];           // (r*h) split lo
__device__ unsigned g_bar_count;
__device__ volatile unsigned g_bar_gen;

// ============================================================================
// helpers
// ============================================================================
__device__ __forceinline__ uint32_t smem_to_u32(const void* p) {
    uint32_t a;
    asm("{ .reg .u64 t; cvta.to.shared.u64 t, %1; cvt.u32.u64 %0, t; }"
        : "=r"(a) : "l"(p));
    return a;
}
__device__ __forceinline__ void cp16(uint32_t dst, const void* src) {
    asm volatile("cp.async.cg.shared.global [%0], [%1], 16;"
                 :: "r"(dst), "l"(src));
}
#define CP_COMMIT() asm volatile("cp.async.commit_group;" ::: "memory")
#define CP_WAIT(n)  asm volatile("cp.async.wait_group %0;" :: "n"(n) : "memory")

#define LDSM_X4(r0, r1, r2, r3, addr) \
    asm volatile("ldmatrix.sync.aligned.m8n8.x4.shared.b16 {%0,%1,%2,%3}, [%4];" \
                 : "=r"(r0), "=r"(r1), "=r"(r2), "=r"(r3) : "r"(addr))

#define MMA_BF16(d, a, b) \
    asm volatile("mma.sync.aligned.m16n8k16.row.col.f32.bf16.bf16.f32 " \
                 "{%0,%1,%2,%3}, {%4,%5,%6,%7}, {%8,%9}, {%0,%1,%2,%3};" \
                 : "+f"((d)[0]), "+f"((d)[1]), "+f"((d)[2]), "+f"((d)[3]) \
                 : "r"((a)[0]), "r"((a)[1]), "r"((a)[2]), "r"((a)[3]), \
                   "r"((b)[0]), "r"((b)[1]))

// ============================================================================
// split-convert: fp32 -> (bf16 hi, bf16 lo = bf16(x - float(hi)))
// ============================================================================
__global__ void conv_split(const float* __restrict__ src,
                           __nv_bfloat16* __restrict__ dh,
                           __nv_bfloat16* __restrict__ dl, int n4) {
    int i = blockIdx.x * 256 + threadIdx.x;
    if (i >= n4) return;
    float4 v = *(const float4*)(src + (size_t)i * 4);
    __nv_bfloat16 h0 = __float2bfloat16(v.x);
    __nv_bfloat16 h1 = __float2bfloat16(v.y);
    __nv_bfloat16 h2 = __float2bfloat16(v.z);
    __nv_bfloat16 h3 = __float2bfloat16(v.w);
    __nv_bfloat162 ph0, ph1, pl0, pl1;
    ph0.x = h0; ph0.y = h1; ph1.x = h2; ph1.y = h3;
    pl0.x = __float2bfloat16(v.x - __bfloat162float(h0));
    pl0.y = __float2bfloat16(v.y - __bfloat162float(h1));
    pl1.x = __float2bfloat16(v.z - __bfloat162float(h2));
    pl1.y = __float2bfloat16(v.w - __bfloat162float(h3));
    *(__nv_bfloat162*)(dh + (size_t)i * 4)     = ph0;
    *(__nv_bfloat162*)(dh + (size_t)i * 4 + 2) = ph1;
    *(__nv_bfloat162*)(dl + (size_t)i * 4)     = pl0;
    *(__nv_bfloat162*)(dl + (size_t)i * 4 + 2) = pl1;
}

// ============================================================================
// HMMA input GEMM (unchanged from passing round 4)
// ============================================================================
#define KT       32
#define NKT      (DIN / KT)
#define TSTRB    80
#define TILE_SB  (128 * TSTRB)
#define STAGE_SB (4 * TILE_SB)
#define GEMM_SM  (2 * STAGE_SB)

__global__ __launch_bounds__(256)
void gemm_input_tc(const float* __restrict__ bu, const float* __restrict__ br,
                   const float* __restrict__ bc) {
    extern __shared__ char smem[];
    const uint32_t sm0 = smem_to_u32(smem);

    const int g  = blockIdx.z;
    const int n0 = blockIdx.x * 128;
    const int m0 = blockIdx.y * 128;
    const float* bias = (g == 0) ? bu : (g == 1) ? br : bc;
    float* X = g_X + (size_t)g * TBROWS * DH;

    const int tid  = threadIdx.x;
    const int lane = tid & 31;
    const int wm   = (tid >> 5) & 3;
    const int wn   = tid >> 7;

    const int p = tid >> 6;
    const int q = tid & 63;
    const __nv_bfloat16* srcb;
    if (p == 0)      srcb = g_Ah + (size_t)(m0 + q) * DIN;
    else if (p == 1) srcb = g_Al + (size_t)(m0 + q) * DIN;
    else if (p == 2) srcb = g_Bh + ((size_t)g * DH + n0 + q) * DIN;
    else             srcb = g_Bl + ((size_t)g * DH + n0 + q) * DIN;
    const uint32_t dstb = sm0 + p * TILE_SB + q * TSTRB;

    float acc[2][8][4];
#pragma unroll
    for (int mf = 0; mf < 2; mf++)
#pragma unroll
        for (int nf = 0; nf < 8; nf++)
#pragma unroll
            for (int e = 0; e < 4; e++) acc[mf][nf][e] = 0.f;

#pragma unroll
    for (int j = 0; j < 4; j++) {
        cp16(dstb + j * 16,               srcb + j * 8);
        cp16(dstb + 64 * TSTRB + j * 16,  srcb + (size_t)64 * DIN + j * 8);
    }
    CP_COMMIT();

    for (int c = 0; c < NKT; c++) {
        const uint32_t sb = sm0 + (c & 1) * STAGE_SB;
        if (c + 1 < NKT) {
            const uint32_t d2 = sm0 + ((c + 1) & 1) * STAGE_SB
                              + p * TILE_SB + q * TSTRB;
            const __nv_bfloat16* s2 = srcb + (c + 1) * KT;
#pragma unroll
            for (int j = 0; j < 4; j++) {
                cp16(d2 + j * 16,              s2 + j * 8);
                cp16(d2 + 64 * TSTRB + j * 16, s2 + (size_t)64 * DIN + j * 8);
            }
            CP_COMMIT();
            CP_WAIT(1);
        } else {
            CP_WAIT(0);
        }
        __syncthreads();

        const uint32_t arow = (lane & 15);
        const uint32_t acol = (lane >> 4) * 16;
#pragma unroll
        for (int s = 0; s < 2; s++) {
            uint32_t ah[2][4], al[2][4], bh[8][2], bl[8][2];
#pragma unroll
            for (int mf = 0; mf < 2; mf++) {
                uint32_t ra = sb + (32 * wm + 16 * mf + arow) * TSTRB + acol + s * 32;
                LDSM_X4(ah[mf][0], ah[mf][1], ah[mf][2], ah[mf][3], ra);
                LDSM_X4(al[mf][0], al[mf][1], al[mf][2], al[mf][3], ra + TILE_SB);
            }
#pragma unroll
            for (int nfp = 0; nfp < 4; nfp++) {
                uint32_t rb = sb + 2 * TILE_SB
                            + (64 * wn + 16 * nfp + arow) * TSTRB + acol + s * 32;
                uint32_t r0, r1, r2, r3;
                LDSM_X4(r0, r1, r2, r3, rb);
                bh[2 * nfp][0] = r0; bh[2 * nfp][1] = r2;
                bh[2 * nfp + 1][0] = r1; bh[2 * nfp + 1][1] = r3;
                LDSM_X4(r0, r1, r2, r3, rb + TILE_SB);
                bl[2 * nfp][0] = r0; bl[2 * nfp][1] = r2;
                bl[2 * nfp + 1][0] = r1; bl[2 * nfp + 1][1] = r3;
            }
#pragma unroll
            for (int mf = 0; mf < 2; mf++)
#pragma unroll
                for (int nf = 0; nf < 8; nf++) {
                    MMA_BF16(acc[mf][nf], ah[mf], bh[nf]);
                    MMA_BF16(acc[mf][nf], ah[mf], bl[nf]);
                    MMA_BF16(acc[mf][nf], al[mf], bh[nf]);
                }
        }
        __syncthreads();
    }

#pragma unroll
    for (int mf = 0; mf < 2; mf++) {
        int row0 = m0 + wm * 32 + mf * 16 + (lane >> 2);
#pragma unroll
        for (int nf = 0; nf < 8; nf++) {
            int col = n0 + wn * 64 + nf * 8 + (lane & 3) * 2;
            float2 bv = *(const float2*)(bias + col);
            float2 o0 = make_float2(acc[mf][nf][0] + bv.x, acc[mf][nf][1] + bv.y);
            float2 o1 = make_float2(acc[mf][nf][2] + bv.x, acc[mf][nf][3] + bv.y);
            *(float2*)(X + (size_t)row0 * DH + col)       = o0;
            *(float2*)(X + (size_t)(row0 + 8) * DH + col) = o1;
        }
    }
}

// ============================================================================
// Software grid barrier (monotonic; nanosleep backoff in the spin)
// ============================================================================
__device__ __forceinline__ void grid_barrier(unsigned& lgen) {
    __syncthreads();
    if (threadIdx.x == 0) {
        unsigned target = ++lgen;
        __threadfence();
        unsigned arr = atomicAdd(&g_bar_count, 1u) + 1u;
        if (arr == target * NBLK) {
            __threadfence();
            g_bar_gen = target;
        } else {
            while (g_bar_gen < target) { __nanosleep(20); }
        }
        __threadfence();
    }
    __syncthreads();
}

// ============================================================================
// init: h <- hx (fp32 + bf16 split), reset barrier state
// ============================================================================
__global__ void init_h(const float* __restrict__ hx) {
    int i = blockIdx.x * 256 + threadIdx.x;
    float v = hx[i];
    g_h[i] = v;
    __nv_bfloat16 hi = __float2bfloat16(v);
    g_hh[i] = hi;
    g_hl[i] = __float2bfloat16(v - __bfloat162float(hi));
    if (i == 0) { g_bar_count = 0u; g_bar_gen = 0u; }
}

// ============================================================================
// Persistent tensor-core recurrence.
// SMEM map (bytes):
//   [0, 81920)        wsA: phase-A weight slice, [half][ktile32][16 rows][80B]
//   [81920, 122880)   wsB: phase-B weight slice, [half][ktile32][8 rows][80B]
//   [122880, 204800)  h staging double buffer, 2 x [half][ktile4][64 rows][80B]
//                     (aliased as reduction scratch between GEMM and epilogue)
// ============================================================================
#define WSA_HALF 40960
#define WSB_HALF 20480
#define SM_WSA   0
#define SM_WSB   81920
#define SM_HBUF  122880
#define HB_HALF  20480
#define HB_SZ    40960
#define PERS_SM  204800
#define REDA_W   1288     // fp32 words per warp slice, phase A (64 rows x 20)
#define REDB_W   648      // phase B (64 rows x 10)

__device__ __forceinline__ void stage_h(uint32_t dst, const __nv_bfloat16* hi,
                                        const __nv_bfloat16* lo, int k0) {
    const int kt  = threadIdx.x >> 6;
    const int row = threadIdx.x & 63;
    uint32_t d = dst + kt * 5120 + row * 80;
    const __nv_bfloat16* sh = hi + row * DH + k0 + kt * 32;
    const __nv_bfloat16* sl = lo + row * DH + k0 + kt * 32;
#pragma unroll
    for (int j = 0; j < 4; j++) {
        cp16(d + j * 16,            sh + j * 8);
        cp16(d + HB_HALF + j * 16,  sl + j * 8);
    }
}

__global__ __launch_bounds__(NTHR, 1)
void gru_pers_tc(const float* __restrict__ Wu, const float* __restrict__ Wr,
                 const float* __restrict__ Wc, float* __restrict__ out,
                 int write_tail) {
    extern __shared__ char sm[];
    const uint32_t sm0 = smem_to_u32(sm);
    float* red = (float*)(sm + SM_HBUF);

    const int tid  = threadIdx.x;
    const int wid  = tid >> 5;
    const int lane = tid & 31;
    const int b    = blockIdx.x;
    const int gA   = b >> 6;            // 0: update cols, 1: reset cols
    const int n0A  = (b & 63) * 16;
    const int n0B  = b * 8;
    const float* WA = gA ? Wr : Wu;

    // ---- one-time: split W_hh slices into smem (80B-stride ktile layout)
    for (int e = tid; e < 16 * 512; e += NTHR) {
        int row = e >> 9, k = (e & 511) * 2;
        float2 v = *(const float2*)(WA + (size_t)(n0A + row) * DH + k);
        __nv_bfloat162 hi2, lo2;
        hi2.x = __float2bfloat16(v.x); hi2.y = __float2bfloat16(v.y);
        lo2.x = __float2bfloat16(v.x - __bfloat162float(hi2.x));
        lo2.y = __float2bfloat16(v.y - __bfloat162float(hi2.y));
        uint32_t ad = SM_WSA + (k >> 5) * 1280 + row * 80 + (k & 31) * 2;
        *(__nv_bfloat162*)(sm + ad)            = hi2;
        *(__nv_bfloat162*)(sm + ad + WSA_HALF) = lo2;
    }
    for (int e = tid; e < 8 * 512; e += NTHR) {
        int row = e >> 9, k = (e & 511) * 2;
        float2 v = *(const float2*)(Wc + (size_t)(n0B + row) * DH + k);
        __nv_bfloat162 hi2, lo2;
        hi2.x = __float2bfloat16(v.x); hi2.y = __float2bfloat16(v.y);
        lo2.x = __float2bfloat16(v.x - __bfloat162float(hi2.x));
        lo2.y = __float2bfloat16(v.y - __bfloat162float(hi2.y));
        uint32_t ad = SM_WSB + (k >> 5) * 640 + row * 80 + (k & 31) * 2;
        *(__nv_bfloat162*)(sm + ad)            = hi2;
        *(__nv_bfloat162*)(sm + ad + WSB_HALF) = lo2;
    }
    __syncthreads();

    const int ktl = wid >> 1;           // warp's ktile within chunk (0..3)
    const int s   = wid & 1;            // warp's k16 half within ktile
    unsigned lgen = 0;

    for (int t = 0; t < T_STEPS; t++) {
        // ======================= PHASE A (u, r) =======================
        float acc[4][2][4];
#pragma unroll
        for (int mf = 0; mf < 4; mf++)
#pragma unroll
            for (int nf = 0; nf < 2; nf++)
#pragma unroll
                for (int e = 0; e < 4; e++) acc[mf][nf][e] = 0.f;

        stage_h(sm0 + SM_HBUF, g_hh, g_hl, 0);
        CP_COMMIT();

        for (int c = 0; c < 8; c++) {
            if (c < 7) {
                stage_h(sm0 + SM_HBUF + ((c + 1) & 1) * HB_SZ, g_hh, g_hl,
                        (c + 1) * 128);
                CP_COMMIT();
                CP_WAIT(1);
            } else {
                CP_WAIT(0);
            }
            __syncthreads();

            const uint32_t hb = sm0 + SM_HBUF + (c & 1) * HB_SZ;
            uint32_t bA = sm0 + SM_WSA + (c * 4 + ktl) * 1280
                        + (lane & 15) * 80 + (lane >> 4) * 16 + s * 32;
            uint32_t r0, r1, r2, r3;
            uint32_t bh0[2], bh1[2], bl0[2], bl1[2];
            LDSM_X4(r0, r1, r2, r3, bA);
            bh0[0] = r0; bh0[1] = r2; bh1[0] = r1; bh1[1] = r3;
            LDSM_X4(r0, r1, r2, r3, bA + WSA_HALF);
            bl0[0] = r0; bl0[1] = r2; bl1[0] = r1; bl1[1] = r3;
#pragma unroll
            for (int mf = 0; mf < 4; mf++) {
                uint32_t ra = hb + ktl * 5120 + (mf * 16 + (lane & 15)) * 80
                            + (lane >> 4) * 16 + s * 32;
                uint32_t ah[4], al[4];
                LDSM_X4(ah[0], ah[1], ah[2], ah[3], ra);
                LDSM_X4(al[0], al[1], al[2], al[3], ra + HB_HALF);
                MMA_BF16(acc[mf][0], ah, bh0);
                MMA_BF16(acc[mf][0], ah, bl0);
                MMA_BF16(acc[mf][0], al, bh0);
                MMA_BF16(acc[mf][1], ah, bh1);
                MMA_BF16(acc[mf][1], ah, bl1);
                MMA_BF16(acc[mf][1], al, bh1);
            }
            __syncthreads();
        }

        // ---- cross-warp reduction (8 partials of 64x16)
        {
            float* rw = red + wid * REDA_W;
#pragma unroll
            for (int mf = 0; mf < 4; mf++)
#pragma unroll
                for (int nf = 0; nf < 2; nf++) {
                    int row = mf * 16 + (lane >> 2);
                    int col = nf * 8 + (lane & 3) * 2;
                    *(float2*)&rw[row * 20 + col] =
                        make_float2(acc[mf][nf][0], acc[mf][nf][1]);
                    *(float2*)&rw[(row + 8) * 20 + col] =
                        make_float2(acc[mf][nf][2], acc[mf][nf][3]);
                }
        }
        __syncthreads();
        {
            const int m  = tid >> 2;
            const int cb = (tid & 3) * 4;
            float4 sv = make_float4(0.f, 0.f, 0.f, 0.f);
#pragma unroll
            for (int w = 0; w < 8; w++) {
                float4 v = *(float4*)&red[w * REDA_W + m * 20 + cb];
                sv.x += v.x; sv.y += v.y; sv.z += v.z; sv.w += v.w;
            }
            const int n = n0A + cb;
            const float* Xg = g_X + ((size_t)gA * TBROWS + (size_t)t * B_SZ) * DH
                            + m * DH + n;
            float s0 = 1.f / (1.f + expf(-(sv.x + Xg[0])));
            float s1 = 1.f / (1.f + expf(-(sv.y + Xg[1])));
            float s2 = 1.f / (1.f + expf(-(sv.z + Xg[2])));
            float s3 = 1.f / (1.f + expf(-(sv.w + Xg[3])));
            if (gA == 0) {
                *(float4*)&g_u[m * DH + n] = make_float4(s0, s1, s2, s3);
            } else {
                float4 hv = *(float4*)&g_h[m * DH + n];
                float r0f = s0 * hv.x, r1f = s1 * hv.y;
                float r2f = s2 * hv.z, r3f = s3 * hv.w;
                __nv_bfloat162 h01, h23, l01, l23;
                h01.x = __float2bfloat16(r0f); h01.y = __float2bfloat16(r1f);
                h23.x = __float2bfloat16(r2f); h23.y = __float2bfloat16(r3f);
                l01.x = __float2bfloat16(r0f - __bfloat162float(h01.x));
                l01.y = __float2bfloat16(r1f - __bfloat162float(h01.y));
                l23.x = __float2bfloat16(r2f - __bfloat162float(h23.x));
                l23.y = __float2bfloat16(r3f - __bfloat162float(h23.y));
                *(__nv_bfloat162*)&g_rhh[m * DH + n]     = h01;
                *(__nv_bfloat162*)&g_rhh[m * DH + n + 2] = h23;
                *(__nv_bfloat162*)&g_rhl[m * DH + n]     = l01;
                *(__nv_bfloat162*)&g_rhl[m * DH + n + 2] = l23;
            }
        }
        grid_barrier(lgen);

        // ======================= PHASE B (candidate + update) =============
        float accB[4][4];
#pragma unroll
        for (int mf = 0; mf < 4; mf++)
#pragma unroll
            for (int e = 0; e < 4; e++) accB[mf][e] = 0.f;

        stage_h(sm0 + SM_HBUF, g_rhh, g_rhl, 0);
        CP_COMMIT();

        for (int c = 0; c < 8; c++) {
            if (c < 7) {
                stage_h(sm0 + SM_HBUF + ((c + 1) & 1) * HB_SZ, g_rhh, g_rhl,
                        (c + 1) * 128);
                CP_COMMIT();
                CP_WAIT(1);
            } else {
                CP_WAIT(0);
            }
            __syncthreads();

            const uint32_t hb = sm0 + SM_HBUF + (c & 1) * HB_SZ;
            uint32_t bB = sm0 + SM_WSB + (c * 4 + ktl) * 640
                        + (lane & 7) * 80 + (lane >> 3) * 16;
            uint32_t r0, r1, r2, r3;
            uint32_t bh[2], bl[2];
            LDSM_X4(r0, r1, r2, r3, bB);
            if (s == 0) { bh[0] = r0; bh[1] = r1; } else { bh[0] = r2; bh[1] = r3; }
            LDSM_X4(r0, r1, r2, r3, bB + WSB_HALF);
            if (s == 0) { bl[0] = r0; bl[1] = r1; } else { bl[0] = r2; bl[1] = r3; }
#pragma unroll
            for (int mf = 0; mf < 4; mf++) {
                uint32_t ra = hb + ktl * 5120 + (mf * 16 + (lane & 15)) * 80
                            + (lane >> 4) * 16 + s * 32;
                uint32_t ah[4], al[4];
                LDSM_X4(ah[0], ah[1], ah[2], ah[3], ra);
                LDSM_X4(al[0], al[1], al[2], al[3], ra + HB_HALF);
                MMA_BF16(accB[mf], ah, bh);
                MMA_BF16(accB[mf], ah, bl);
                MMA_BF16(accB[mf], al, bh);
            }
            __syncthreads();
        }

        // ---- reduction (8 partials of 64x8)
        {
            float* rw = red + wid * REDB_W;
#pragma unroll
            for (int mf = 0; mf < 4; mf++) {
                int row = mf * 16 + (lane >> 2);
                int col = (lane & 3) * 2;
                *(float2*)&rw[row * 10 + col] =
                    make_float2(accB[mf][0], accB[mf][1]);
                *(float2*)&rw[(row + 8) * 10 + col] =
                    make_float2(accB[mf][2], accB[mf][3]);
            }
        }
        __syncthreads();
        {
            const int m  = tid >> 2;
            const int cb = (tid & 3) * 2;
            float2 sv = make_float2(0.f, 0.f);
#pragma unroll
            for (int w = 0; w < 8; w++) {
                float2 v = *(float2*)&red[w * REDB_W + m * 10 + cb];
                sv.x += v.x; sv.y += v.y;
            }
            const int n = n0B + cb;
            const float* Xc = g_X + (2ull * TBROWS + (size_t)t * B_SZ) * DH
                            + m * DH + n;
            float c0 = tanhf(sv.x + Xc[0]);
            float c1 = tanhf(sv.y + Xc[1]);
            float2 uv = *(float2*)&g_u[m * DH + n];
            float2 hv = *(float2*)&g_h[m * DH + n];
            float hn0 = (1.f - uv.x) * hv.x + uv.x * c0;
            float hn1 = (1.f - uv.y) * hv.y + uv.y * c1;
            *(float2*)&g_h[m * DH + n] = make_float2(hn0, hn1);
            __nv_bfloat162 hh2, hl2;
            hh2.x = __float2bfloat16(hn0); hh2.y = __float2bfloat16(hn1);
            hl2.x = __float2bfloat16(hn0 - __bfloat162float(hh2.x));
            hl2.y = __float2bfloat16(hn1 - __bfloat162float(hh2.y));
            *(__nv_bfloat162*)&g_hh[m * DH + n] = hh2;
            *(__nv_bfloat162*)&g_hl[m * DH + n] = hl2;
            size_t ob = ((size_t)t * B_SZ + m) * DH + n;
            *(float2*)&out[ob] = make_float2(hn0, hn1);
            if (write_tail && t == T_STEPS - 1) {
                size_t tb = ((size_t)T_STEPS * B_SZ + m) * DH + n;
                *(float2*)&out[tb] = make_float2(hn0, hn1);
            }
        }
        grid_barrier(lgen);
    }
}

// ============================================================================
// Launch
// ============================================================================
extern "C" void kernel_launch(void* const* d_in, const int* in_sizes, int n_in,
                              void* d_out, int out_size) {
    const float* emb    = (const float*)d_in[0];
    const float* hx     = (const float*)d_in[1];
    const float* w_ih_u = (const float*)d_in[2];
    const float* w_ih_r = (const float*)d_in[3];
    const float* w_ih_c = (const float*)d_in[4];
    const float* w_hh_u = (const float*)d_in[5];
    const float* w_hh_r = (const float*)d_in[6];
    const float* w_hh_c = (const float*)d_in[7];
    const float* b_u    = (const float*)d_in[8];
    const float* b_r    = (const float*)d_in[9];
    const float* b_c    = (const float*)d_in[10];
    float* out = (float*)d_out;

    const long long main_elems = (long long)T_STEPS * B_SZ * DH;
    int write_tail = ((long long)out_size >= main_elems + (long long)B_SZ * DH) ? 1 : 0;

    cudaFuncSetAttribute(gemm_input_tc,
                         cudaFuncAttributeMaxDynamicSharedMemorySize, GEMM_SM);
    cudaFuncSetAttribute(gru_pers_tc,
                         cudaFuncAttributeMaxDynamicSharedMemorySize, PERS_SM);

    __nv_bfloat16 *pAh, *pAl, *pBh, *pBl;
    cudaGetSymbolAddress((void**)&pAh, g_Ah);
    cudaGetSymbolAddress((void**)&pAl, g_Al);
    cudaGetSymbolAddress((void**)&pBh, g_Bh);
    cudaGetSymbolAddress((void**)&pBl, g_Bl);

    {
        int n4 = TBROWS * DIN / 4;
        conv_split<<<(n4 + 255) / 256, 256>>>(emb, pAh, pAl, n4);
        int w4 = DH * DIN / 4;
        conv_split<<<(w4 + 255) / 256, 256>>>(w_ih_u, pBh, pBl, w4);
        conv_split<<<(w4 + 255) / 256, 256>>>(w_ih_r, pBh + (size_t)DH * DIN,
                                              pBl + (size_t)DH * DIN, w4);
        conv_split<<<(w4 + 255) / 256, 256>>>(w_ih_c, pBh + 2ull * DH * DIN,
                                              pBl + 2ull * DH * DIN, w4);
    }

    dim3 g1(DH / 128, TBROWS / 128, 3);
    gemm_input_tc<<<g1, 256, GEMM_SM>>>(b_u, b_r, b_c);
    init_h<<<(B_SZ * DH) / 256, 256>>>(hx);
    gru_pers_tc<<<NBLK, NTHR, PERS_SM>>>(w_hh_u, w_hh_r, w_hh_c, out, write_tail);
}

// round 7
// speedup vs baseline: 1.5805x; 1.1327x over previous
#include <cuda_runtime.h>
#include <cuda_bf16.h>
#include <math.h>
#include <stdint.h>

#define T_STEPS 512
#define B_SZ    64
#define DIN     1024
#define DH      1024
#define TBROWS  (T_STEPS * B_SZ)   // 32768

#define NBLK 128
#define NTHR 256

// ---------------- device scratch (static; no allocation allowed) -------------
__device__ float g_X[3ull * TBROWS * DH];            // x@Wih^T + b, per gate
__device__ __nv_bfloat16 g_Ah[(size_t)TBROWS * DIN]; // emb split hi
__device__ __nv_bfloat16 g_Al[(size_t)TBROWS * DIN]; // emb split lo
__device__ __nv_bfloat16 g_Bh[3ull * DH * DIN];      // w_ih split hi (3 gates)
__device__ __nv_bfloat16 g_Bl[3ull * DH * DIN];      // w_ih split lo
__device__ float g_h [B_SZ * DH];                    // hidden state fp32
__device__ float g_u [B_SZ * DH];                    // update gate
__device__ __nv_bfloat16 g_hh [B_SZ * DH];           // h split hi
__device__ __nv_bfloat16 g_hl [B_SZ * DH];           // h split lo
__device__ __nv_bfloat16 g_rhh[B_SZ * DH];           // (r*h) split hi
__device__ __nv_bfloat16 g_rhl[B_SZ * DH];           // (r*h) split lo
__device__ unsigned g_bar_count;
__device__ volatile unsigned g_bar_gen;

// ============================================================================
// helpers
// ============================================================================
__device__ __forceinline__ uint32_t smem_to_u32(const void* p) {
    uint32_t a;
    asm("{ .reg .u64 t; cvta.to.shared.u64 t, %1; cvt.u32.u64 %0, t; }"
        : "=r"(a) : "l"(p));
    return a;
}
__device__ __forceinline__ void cp16(uint32_t dst, const void* src) {
    asm volatile("cp.async.cg.shared.global [%0], [%1], 16;"
                 :: "r"(dst), "l"(src));
}
#define CP_COMMIT() asm volatile("cp.async.commit_group;" ::: "memory")
#define CP_WAIT(n)  asm volatile("cp.async.wait_group %0;" :: "n"(n) : "memory")

#define LDSM_X4(r0, r1, r2, r3, addr) \
    asm volatile("ldmatrix.sync.aligned.m8n8.x4.shared.b16 {%0,%1,%2,%3}, [%4];" \
                 : "=r"(r0), "=r"(r1), "=r"(r2), "=r"(r3) : "r"(addr))

#define MMA_BF16(d, a, b) \
    asm volatile("mma.sync.aligned.m16n8k16.row.col.f32.bf16.bf16.f32 " \
                 "{%0,%1,%2,%3}, {%4,%5,%6,%7}, {%8,%9}, {%0,%1,%2,%3};" \
                 : "+f"((d)[0]), "+f"((d)[1]), "+f"((d)[2]), "+f"((d)[3]) \
                 : "r"((a)[0]), "r"((a)[1]), "r"((a)[2]), "r"((a)[3]), \
                   "r"((b)[0]), "r"((b)[1]))

// ============================================================================
// split-convert: fp32 -> (bf16 hi, bf16 lo = bf16(x - float(hi)))
// ============================================================================
__global__ void conv_split(const float* __restrict__ src,
                           __nv_bfloat16* __restrict__ dh,
                           __nv_bfloat16* __restrict__ dl, int n4) {
    int i = blockIdx.x * 256 + threadIdx.x;
    if (i >= n4) return;
    float4 v = *(const float4*)(src + (size_t)i * 4);
    __nv_bfloat16 h0 = __float2bfloat16(v.x);
    __nv_bfloat16 h1 = __float2bfloat16(v.y);
    __nv_bfloat16 h2 = __float2bfloat16(v.z);
    __nv_bfloat16 h3 = __float2bfloat16(v.w);
    __nv_bfloat162 ph0, ph1, pl0, pl1;
    ph0.x = h0; ph0.y = h1; ph1.x = h2; ph1.y = h3;
    pl0.x = __float2bfloat16(v.x - __bfloat162float(h0));
    pl0.y = __float2bfloat16(v.y - __bfloat162float(h1));
    pl1.x = __float2bfloat16(v.z - __bfloat162float(h2));
    pl1.y = __float2bfloat16(v.w - __bfloat162float(h3));
    *(__nv_bfloat162*)(dh + (size_t)i * 4)     = ph0;
    *(__nv_bfloat162*)(dh + (size_t)i * 4 + 2) = ph1;
    *(__nv_bfloat162*)(dl + (size_t)i * 4)     = pl0;
    *(__nv_bfloat162*)(dl + (size_t)i * 4 + 2) = pl1;
}

// ============================================================================
// HMMA input GEMM (unchanged from passing round 4/6)
// ============================================================================
#define KT       32
#define NKT      (DIN / KT)
#define TSTRB    80
#define TILE_SB  (128 * TSTRB)
#define STAGE_SB (4 * TILE_SB)
#define GEMM_SM  (2 * STAGE_SB)

__global__ __launch_bounds__(256)
void gemm_input_tc(const float* __restrict__ bu, const float* __restrict__ br,
                   const float* __restrict__ bc) {
    extern __shared__ char smem[];
    const uint32_t sm0 = smem_to_u32(smem);

    const int g  = blockIdx.z;
    const int n0 = blockIdx.x * 128;
    const int m0 = blockIdx.y * 128;
    const float* bias = (g == 0) ? bu : (g == 1) ? br : bc;
    float* X = g_X + (size_t)g * TBROWS * DH;

    const int tid  = threadIdx.x;
    const int lane = tid & 31;
    const int wm   = (tid >> 5) & 3;
    const int wn   = tid >> 7;

    const int p = tid >> 6;
    const int q = tid & 63;
    const __nv_bfloat16* srcb;
    if (p == 0)      srcb = g_Ah + (size_t)(m0 + q) * DIN;
    else if (p == 1) srcb = g_Al + (size_t)(m0 + q) * DIN;
    else if (p == 2) srcb = g_Bh + ((size_t)g * DH + n0 + q) * DIN;
    else             srcb = g_Bl + ((size_t)g * DH + n0 + q) * DIN;
    const uint32_t dstb = sm0 + p * TILE_SB + q * TSTRB;

    float acc[2][8][4];
#pragma unroll
    for (int mf = 0; mf < 2; mf++)
#pragma unroll
        for (int nf = 0; nf < 8; nf++)
#pragma unroll
            for (int e = 0; e < 4; e++) acc[mf][nf][e] = 0.f;

#pragma unroll
    for (int j = 0; j < 4; j++) {
        cp16(dstb + j * 16,               srcb + j * 8);
        cp16(dstb + 64 * TSTRB + j * 16,  srcb + (size_t)64 * DIN + j * 8);
    }
    CP_COMMIT();

    for (int c = 0; c < NKT; c++) {
        const uint32_t sb = sm0 + (c & 1) * STAGE_SB;
        if (c + 1 < NKT) {
            const uint32_t d2 = sm0 + ((c + 1) & 1) * STAGE_SB
                              + p * TILE_SB + q * TSTRB;
            const __nv_bfloat16* s2 = srcb + (c + 1) * KT;
#pragma unroll
            for (int j = 0; j < 4; j++) {
                cp16(d2 + j * 16,              s2 + j * 8);
                cp16(d2 + 64 * TSTRB + j * 16, s2 + (size_t)64 * DIN + j * 8);
            }
            CP_COMMIT();
            CP_WAIT(1);
        } else {
            CP_WAIT(0);
        }
        __syncthreads();

        const uint32_t arow = (lane & 15);
        const uint32_t acol = (lane >> 4) * 16;
#pragma unroll
        for (int s = 0; s < 2; s++) {
            uint32_t ah[2][4], al[2][4], bh[8][2], bl[8][2];
#pragma unroll
            for (int mf = 0; mf < 2; mf++) {
                uint32_t ra = sb + (32 * wm + 16 * mf + arow) * TSTRB + acol + s * 32;
                LDSM_X4(ah[mf][0], ah[mf][1], ah[mf][2], ah[mf][3], ra);
                LDSM_X4(al[mf][0], al[mf][1], al[mf][2], al[mf][3], ra + TILE_SB);
            }
#pragma unroll
            for (int nfp = 0; nfp < 4; nfp++) {
                uint32_t rb = sb + 2 * TILE_SB
                            + (64 * wn + 16 * nfp + arow) * TSTRB + acol + s * 32;
                uint32_t r0, r1, r2, r3;
                LDSM_X4(r0, r1, r2, r3, rb);
                bh[2 * nfp][0] = r0; bh[2 * nfp][1] = r2;
                bh[2 * nfp + 1][0] = r1; bh[2 * nfp + 1][1] = r3;
                LDSM_X4(r0, r1, r2, r3, rb + TILE_SB);
                bl[2 * nfp][0] = r0; bl[2 * nfp][1] = r2;
                bl[2 * nfp + 1][0] = r1; bl[2 * nfp + 1][1] = r3;
            }
#pragma unroll
            for (int mf = 0; mf < 2; mf++)
#pragma unroll
                for (int nf = 0; nf < 8; nf++) {
                    MMA_BF16(acc[mf][nf], ah[mf], bh[nf]);
                    MMA_BF16(acc[mf][nf], ah[mf], bl[nf]);
                    MMA_BF16(acc[mf][nf], al[mf], bh[nf]);
                }
        }
        __syncthreads();
    }

#pragma unroll
    for (int mf = 0; mf < 2; mf++) {
        int row0 = m0 + wm * 32 + mf * 16 + (lane >> 2);
#pragma unroll
        for (int nf = 0; nf < 8; nf++) {
            int col = n0 + wn * 64 + nf * 8 + (lane & 3) * 2;
            float2 bv = *(const float2*)(bias + col);
            float2 o0 = make_float2(acc[mf][nf][0] + bv.x, acc[mf][nf][1] + bv.y);
            float2 o1 = make_float2(acc[mf][nf][2] + bv.x, acc[mf][nf][3] + bv.y);
            *(float2*)(X + (size_t)row0 * DH + col)       = o0;
            *(float2*)(X + (size_t)(row0 + 8) * DH + col) = o1;
        }
    }
}

// ============================================================================
// Software grid barrier (monotonic; nanosleep backoff in the spin)
// ============================================================================
__device__ __forceinline__ void grid_barrier(unsigned& lgen) {
    __syncthreads();
    if (threadIdx.x == 0) {
        unsigned target = ++lgen;
        __threadfence();
        unsigned arr = atomicAdd(&g_bar_count, 1u) + 1u;
        if (arr == target * NBLK) {
            __threadfence();
            g_bar_gen = target;
        } else {
            while (g_bar_gen < target) { __nanosleep(20); }
        }
        __threadfence();
    }
    __syncthreads();
}

// ============================================================================
// init: h <- hx (fp32 + bf16 split), reset barrier state
// ============================================================================
__global__ void init_h(const float* __restrict__ hx) {
    int i = blockIdx.x * 256 + threadIdx.x;
    float v = hx[i];
    g_h[i] = v;
    __nv_bfloat16 hi = __float2bfloat16(v);
    g_hh[i] = hi;
    g_hl[i] = __float2bfloat16(v - __bfloat162float(hi));
    if (i == 0) { g_bar_count = 0u; g_bar_gen = 0u; }
}

// ============================================================================
// Persistent tensor-core recurrence, warp-autonomous k-streaming.
// SMEM map (bytes):
//   [0, 81920)         wsA: phase-A weight slice [ktile32][16 rows][80B] hi|lo
//   [81920, 122880)    wsB: phase-B weight slice [ktile32][8 rows][80B]  hi|lo
//   [122880, 221184)   per-warp h staging: 8 warps x 12288
//                      (2 stages x {hi 64x48B, lo 64x48B}); aliased per-warp
//                      as reduction scratch after each GEMM loop.
// Warp w owns k in [128w, 128w+128); 8 subiters of 16k, private cp.async chain.
// ============================================================================
#define WSA_HALF 40960
#define WSB_HALF 20480
#define SM_WSA   0
#define SM_WSB   81920
#define SM_STG   122880
#define STG_WARP 12288
#define STG_STAGE 6144      // hi 3072 + lo 3072
#define PERS_SM  221184

// stage one 64-row x 16-k (hi,lo) slice into this warp's buffer (8 cp16/lane)
__device__ __forceinline__ void stage_slice(uint32_t dst,
                                            const __nv_bfloat16* __restrict__ hi,
                                            const __nv_bfloat16* __restrict__ lo,
                                            int kbase) {
    const int lane = threadIdx.x & 31;
#pragma unroll
    for (int rr = 0; rr < 2; rr++) {
        int row = lane + 32 * rr;
        const __nv_bfloat16* sh = hi + row * DH + kbase;
        const __nv_bfloat16* sl = lo + row * DH + kbase;
        uint32_t d = dst + row * 48;
        cp16(d,              sh);
        cp16(d + 16,         sh + 8);
        cp16(d + 3072,       sl);
        cp16(d + 3072 + 16,  sl + 8);
    }
}

__global__ __launch_bounds__(NTHR, 1)
void gru_pers_tc(const float* __restrict__ Wu, const float* __restrict__ Wr,
                 const float* __restrict__ Wc, float* __restrict__ out,
                 int write_tail) {
    extern __shared__ char sm[];
    const uint32_t sm0 = smem_to_u32(sm);
    float* red = (float*)(sm + SM_STG);   // per-warp regions, 3072 floats each

    const int tid  = threadIdx.x;
    const int wid  = tid >> 5;
    const int lane = tid & 31;
    const int b    = blockIdx.x;
    const int gA   = b >> 6;            // 0: update cols, 1: reset cols
    const int n0A  = (b & 63) * 16;
    const int n0B  = b * 8;
    const float* WA = gA ? Wr : Wu;

    // ---- one-time: split W_hh slices into smem (80B-stride ktile layout)
    for (int e = tid; e < 16 * 512; e += NTHR) {
        int row = e >> 9, k = (e & 511) * 2;
        float2 v = *(const float2*)(WA + (size_t)(n0A + row) * DH + k);
        __nv_bfloat162 hi2, lo2;
        hi2.x = __float2bfloat16(v.x); hi2.y = __float2bfloat16(v.y);
        lo2.x = __float2bfloat16(v.x - __bfloat162float(hi2.x));
        lo2.y = __float2bfloat16(v.y - __bfloat162float(hi2.y));
        uint32_t ad = SM_WSA + (k >> 5) * 1280 + row * 80 + (k & 31) * 2;
        *(__nv_bfloat162*)(sm + ad)            = hi2;
        *(__nv_bfloat162*)(sm + ad + WSA_HALF) = lo2;
    }
    for (int e = tid; e < 8 * 512; e += NTHR) {
        int row = e >> 9, k = (e & 511) * 2;
        float2 v = *(const float2*)(Wc + (size_t)(n0B + row) * DH + k);
        __nv_bfloat162 hi2, lo2;
        hi2.x = __float2bfloat16(v.x); hi2.y = __float2bfloat16(v.y);
        lo2.x = __float2bfloat16(v.x - __bfloat162float(hi2.x));
        lo2.y = __float2bfloat16(v.y - __bfloat162float(hi2.y));
        uint32_t ad = SM_WSB + (k >> 5) * 640 + row * 80 + (k & 31) * 2;
        *(__nv_bfloat162*)(sm + ad)            = hi2;
        *(__nv_bfloat162*)(sm + ad + WSB_HALF) = lo2;
    }
    __syncthreads();

    const uint32_t my_stg = sm0 + SM_STG + wid * STG_WARP;
    const int kw = 128 * wid;           // warp's k base
    unsigned lgen = 0;

    for (int t = 0; t < T_STEPS; t++) {
        // ======================= PHASE A (u, r) =======================
        float acc[4][2][4];
#pragma unroll
        for (int mf = 0; mf < 4; mf++)
#pragma unroll
            for (int nf = 0; nf < 2; nf++)
#pragma unroll
                for (int e = 0; e < 4; e++) acc[mf][nf][e] = 0.f;

        stage_slice(my_stg, g_hh, g_hl, kw);
        CP_COMMIT();

#pragma unroll
        for (int j = 0; j < 8; j++) {
            if (j < 7) {
                stage_slice(my_stg + ((j + 1) & 1) * STG_STAGE, g_hh, g_hl,
                            kw + 16 * (j + 1));
                CP_COMMIT();
                CP_WAIT(1);
            } else {
                CP_WAIT(0);
            }
            __syncwarp();

            const int kt = 4 * wid + (j >> 1);
            uint32_t bA = sm0 + SM_WSA + kt * 1280
                        + (lane & 15) * 80 + (lane >> 4) * 16 + (j & 1) * 32;
            uint32_t r0, r1, r2, r3;
            uint32_t bh0[2], bh1[2], bl0[2], bl1[2];
            LDSM_X4(r0, r1, r2, r3, bA);
            bh0[0] = r0; bh0[1] = r2; bh1[0] = r1; bh1[1] = r3;
            LDSM_X4(r0, r1, r2, r3, bA + WSA_HALF);
            bl0[0] = r0; bl0[1] = r2; bl1[0] = r1; bl1[1] = r3;
            const uint32_t ab = my_stg + (j & 1) * STG_STAGE;
#pragma unroll
            for (int mf = 0; mf < 4; mf++) {
                uint32_t ra = ab + (mf * 16 + (lane & 15)) * 48 + (lane >> 4) * 16;
                uint32_t ah[4], al[4];
                LDSM_X4(ah[0], ah[1], ah[2], ah[3], ra);
                LDSM_X4(al[0], al[1], al[2], al[3], ra + 3072);
                MMA_BF16(acc[mf][0], ah, bh0);
                MMA_BF16(acc[mf][0], ah, bl0);
                MMA_BF16(acc[mf][0], al, bh0);
                MMA_BF16(acc[mf][1], ah, bh1);
                MMA_BF16(acc[mf][1], ah, bl1);
                MMA_BF16(acc[mf][1], al, bh1);
            }
        }

        // ---- per-warp partials into own region, then cross-warp reduce
        {
            float* rw = red + wid * 3072;
#pragma unroll
            for (int mf = 0; mf < 4; mf++)
#pragma unroll
                for (int nf = 0; nf < 2; nf++) {
                    int row = mf * 16 + (lane >> 2);
                    int col = nf * 8 + (lane & 3) * 2;
                    *(float2*)&rw[row * 20 + col] =
                        make_float2(acc[mf][nf][0], acc[mf][nf][1]);
                    *(float2*)&rw[(row + 8) * 20 + col] =
                        make_float2(acc[mf][nf][2], acc[mf][nf][3]);
                }
        }
        __syncthreads();
        {
            const int m  = tid >> 2;
            const int cb = (tid & 3) * 4;
            float4 sv = make_float4(0.f, 0.f, 0.f, 0.f);
#pragma unroll
            for (int w = 0; w < 8; w++) {
                float4 v = *(float4*)&red[w * 3072 + m * 20 + cb];
                sv.x += v.x; sv.y += v.y; sv.z += v.z; sv.w += v.w;
            }
            const int n = n0A + cb;
            const float* Xg = g_X + ((size_t)gA * TBROWS + (size_t)t * B_SZ) * DH
                            + m * DH + n;
            float s0 = 1.f / (1.f + expf(-(sv.x + Xg[0])));
            float s1 = 1.f / (1.f + expf(-(sv.y + Xg[1])));
            float s2 = 1.f / (1.f + expf(-(sv.z + Xg[2])));
            float s3 = 1.f / (1.f + expf(-(sv.w + Xg[3])));
            if (gA == 0) {
                *(float4*)&g_u[m * DH + n] = make_float4(s0, s1, s2, s3);
            } else {
                float4 hv = *(float4*)&g_h[m * DH + n];
                float r0f = s0 * hv.x, r1f = s1 * hv.y;
                float r2f = s2 * hv.z, r3f = s3 * hv.w;
                __nv_bfloat162 h01, h23, l01, l23;
                h01.x = __float2bfloat16(r0f); h01.y = __float2bfloat16(r1f);
                h23.x = __float2bfloat16(r2f); h23.y = __float2bfloat16(r3f);
                l01.x = __float2bfloat16(r0f - __bfloat162float(h01.x));
                l01.y = __float2bfloat16(r1f - __bfloat162float(h01.y));
                l23.x = __float2bfloat16(r2f - __bfloat162float(h23.x));
                l23.y = __float2bfloat16(r3f - __bfloat162float(h23.y));
                *(__nv_bfloat162*)&g_rhh[m * DH + n]     = h01;
                *(__nv_bfloat162*)&g_rhh[m * DH + n + 2] = h23;
                *(__nv_bfloat162*)&g_rhl[m * DH + n]     = l01;
                *(__nv_bfloat162*)&g_rhl[m * DH + n + 2] = l23;
            }
        }
        grid_barrier(lgen);

        // ======================= PHASE B (candidate + update) =============
        float accB[4][4];
#pragma unroll
        for (int mf = 0; mf < 4; mf++)
#pragma unroll
            for (int e = 0; e < 4; e++) accB[mf][e] = 0.f;

        stage_slice(my_stg, g_rhh, g_rhl, kw);
        CP_COMMIT();

#pragma unroll
        for (int j = 0; j < 8; j++) {
            if (j < 7) {
                stage_slice(my_stg + ((j + 1) & 1) * STG_STAGE, g_rhh, g_rhl,
                            kw + 16 * (j + 1));
                CP_COMMIT();
                CP_WAIT(1);
            } else {
                CP_WAIT(0);
            }
            __syncwarp();

            const int kt = 4 * wid + (j >> 1);
            const int s  = j & 1;
            uint32_t bB = sm0 + SM_WSB + kt * 640
                        + (lane & 7) * 80 + (lane >> 3) * 16;
            uint32_t r0, r1, r2, r3;
            uint32_t bh[2], bl[2];
            LDSM_X4(r0, r1, r2, r3, bB);
            if (s == 0) { bh[0] = r0; bh[1] = r1; } else { bh[0] = r2; bh[1] = r3; }
            LDSM_X4(r0, r1, r2, r3, bB + WSB_HALF);
            if (s == 0) { bl[0] = r0; bl[1] = r1; } else { bl[0] = r2; bl[1] = r3; }
            const uint32_t ab = my_stg + (j & 1) * STG_STAGE;
#pragma unroll
            for (int mf = 0; mf < 4; mf++) {
                uint32_t ra = ab + (mf * 16 + (lane & 15)) * 48 + (lane >> 4) * 16;
                uint32_t ah[4], al[4];
                LDSM_X4(ah[0], ah[1], ah[2], ah[3], ra);
                LDSM_X4(al[0], al[1], al[2], al[3], ra + 3072);
                MMA_BF16(accB[mf], ah, bh);
                MMA_BF16(accB[mf], ah, bl);
                MMA_BF16(accB[mf], al, bh);
            }
        }

        // ---- reduction (8 partials of 64x8)
        {
            float* rw = red + wid * 3072;
#pragma unroll
            for (int mf = 0; mf < 4; mf++) {
                int row = mf * 16 + (lane >> 2);
                int col = (lane & 3) * 2;
                *(float2*)&rw[row * 10 + col] =
                    make_float2(accB[mf][0], accB[mf][1]);
                *(float2*)&rw[(row + 8) * 10 + col] =
                    make_float2(accB[mf][2], accB[mf][3]);
            }
        }
        __syncthreads();
        {
            const int m  = tid >> 2;
            const int cb = (tid & 3) * 2;
            float2 sv = make_float2(0.f, 0.f);
#pragma unroll
            for (int w = 0; w < 8; w++) {
                float2 v = *(float2*)&red[w * 3072 + m * 10 + cb];
                sv.x += v.x; sv.y += v.y;
            }
            const int n = n0B + cb;
            const float* Xc = g_X + (2ull * TBROWS + (size_t)t * B_SZ) * DH
                            + m * DH + n;
            float c0 = tanhf(sv.x + Xc[0]);
            float c1 = tanhf(sv.y + Xc[1]);
            float2 uv = *(float2*)&g_u[m * DH + n];
            float2 hv = *(float2*)&g_h[m * DH + n];
            float hn0 = (1.f - uv.x) * hv.x + uv.x * c0;
            float hn1 = (1.f - uv.y) * hv.y + uv.y * c1;
            *(float2*)&g_h[m * DH + n] = make_float2(hn0, hn1);
            __nv_bfloat162 hh2, hl2;
            hh2.x = __float2bfloat16(hn0); hh2.y = __float2bfloat16(hn1);
            hl2.x = __float2bfloat16(hn0 - __bfloat162float(hh2.x));
            hl2.y = __float2bfloat16(hn1 - __bfloat162float(hh2.y));
            *(__nv_bfloat162*)&g_hh[m * DH + n] = hh2;
            *(__nv_bfloat162*)&g_hl[m * DH + n] = hl2;
            size_t ob = ((size_t)t * B_SZ + m) * DH + n;
            *(float2*)&out[ob] = make_float2(hn0, hn1);
            if (write_tail && t == T_STEPS - 1) {
                size_t tb = ((size_t)T_STEPS * B_SZ + m) * DH + n;
                *(float2*)&out[tb] = make_float2(hn0, hn1);
            }
        }
        grid_barrier(lgen);
    }
}

// ============================================================================
// Launch
// ============================================================================
extern "C" void kernel_launch(void* const* d_in, const int* in_sizes, int n_in,
                              void* d_out, int out_size) {
    const float* emb    = (const float*)d_in[0];
    const float* hx     = (const float*)d_in[1];
    const float* w_ih_u = (const float*)d_in[2];
    const float* w_ih_r = (const float*)d_in[3];
    const float* w_ih_c = (const float*)d_in[4];
    const float* w_hh_u = (const float*)d_in[5];
    const float* w_hh_r = (const float*)d_in[6];
    const float* w_hh_c = (const float*)d_in[7];
    const float* b_u    = (const float*)d_in[8];
    const float* b_r    = (const float*)d_in[9];
    const float* b_c    = (const float*)d_in[10];
    float* out = (float*)d_out;

    const long long main_elems = (long long)T_STEPS * B_SZ * DH;
    int write_tail = ((long long)out_size >= main_elems + (long long)B_SZ * DH) ? 1 : 0;

    cudaFuncSetAttribute(gemm_input_tc,
                         cudaFuncAttributeMaxDynamicSharedMemorySize, GEMM_SM);
    cudaFuncSetAttribute(gru_pers_tc,
                         cudaFuncAttributeMaxDynamicSharedMemorySize, PERS_SM);

    __nv_bfloat16 *pAh, *pAl, *pBh, *pBl;
    cudaGetSymbolAddress((void**)&pAh, g_Ah);
    cudaGetSymbolAddress((void**)&pAl, g_Al);
    cudaGetSymbolAddress((void**)&pBh, g_Bh);
    cudaGetSymbolAddress((void**)&pBl, g_Bl);

    {
        int n4 = TBROWS * DIN / 4;
        conv_split<<<(n4 + 255) / 256, 256>>>(emb, pAh, pAl, n4);
        int w4 = DH * DIN / 4;
        conv_split<<<(w4 + 255) / 256, 256>>>(w_ih_u, pBh, pBl, w4);
        conv_split<<<(w4 + 255) / 256, 256>>>(w_ih_r, pBh + (size_t)DH * DIN,
                                              pBl + (size_t)DH * DIN, w4);
        conv_split<<<(w4 + 255) / 256, 256>>>(w_ih_c, pBh + 2ull * DH * DIN,
                                              pBl + 2ull * DH * DIN, w4);
    }

    dim3 g1(DH / 128, TBROWS / 128, 3);
    gemm_input_tc<<<g1, 256, GEMM_SM>>>(b_u, b_r, b_c);
    init_h<<<(B_SZ * DH) / 256, 256>>>(hx);
    gru_pers_tc<<<NBLK, NTHR, PERS_SM>>>(w_hh_u, w_hh_r, w_hh_c, out, write_tail);
}

// round 8
// speedup vs baseline: 1.6364x; 1.0353x over previous
#include <cuda_runtime.h>
#include <cuda_bf16.h>
#include <math.h>
#include <stdint.h>

#define T_STEPS 512
#define B_SZ    64
#define DIN     1024
#define DH      1024
#define TBROWS  (T_STEPS * B_SZ)   // 32768

#define NBLK 128
#define NTHR 256

// ---------------- device scratch (static; no allocation allowed) -------------
__device__ float g_X[3ull * TBROWS * DH];            // x@Wih^T + b, per gate
__device__ __nv_bfloat16 g_Ah[(size_t)TBROWS * DIN]; // emb split hi
__device__ __nv_bfloat16 g_Al[(size_t)TBROWS * DIN]; // emb split lo
__device__ __nv_bfloat16 g_Bh[3ull * DH * DIN];      // w_ih split hi (3 gates)
__device__ __nv_bfloat16 g_Bl[3ull * DH * DIN];      // w_ih split lo
__device__ float g_h [B_SZ * DH];                    // hidden state fp32
__device__ float g_u [B_SZ * DH];                    // update gate
__device__ __nv_bfloat16 g_hh [B_SZ * DH];           // h split hi
__device__ __nv_bfloat16 g_hl [B_SZ * DH];           // h split lo
__device__ __nv_bfloat16 g_rhh[B_SZ * DH];           // (r*h) split hi
__device__ __nv_bfloat16 g_rhl[B_SZ * DH];           // (r*h) split lo
__device__ unsigned g_bar_count;
__device__ volatile unsigned g_bar_gen;

// ============================================================================
// helpers
// ============================================================================
__device__ __forceinline__ uint32_t smem_to_u32(const void* p) {
    uint32_t a;
    asm("{ .reg .u64 t; cvta.to.shared.u64 t, %1; cvt.u32.u64 %0, t; }"
        : "=r"(a) : "l"(p));
    return a;
}
__device__ __forceinline__ void cp16(uint32_t dst, const void* src) {
    asm volatile("cp.async.cg.shared.global [%0], [%1], 16;"
                 :: "r"(dst), "l"(src));
}
#define CP_COMMIT() asm volatile("cp.async.commit_group;" ::: "memory")
#define CP_WAIT(n)  asm volatile("cp.async.wait_group %0;" :: "n"(n) : "memory")

#define LDSM_X4(r0, r1, r2, r3, addr) \
    asm volatile("ldmatrix.sync.aligned.m8n8.x4.shared.b16 {%0,%1,%2,%3}, [%4];" \
                 : "=r"(r0), "=r"(r1), "=r"(r2), "=r"(r3) : "r"(addr))

#define MMA_BF16(d, a, b) \
    asm volatile("mma.sync.aligned.m16n8k16.row.col.f32.bf16.bf16.f32 " \
                 "{%0,%1,%2,%3}, {%4,%5,%6,%7}, {%8,%9}, {%0,%1,%2,%3};" \
                 : "+f"((d)[0]), "+f"((d)[1]), "+f"((d)[2]), "+f"((d)[3]) \
                 : "r"((a)[0]), "r"((a)[1]), "r"((a)[2]), "r"((a)[3]), \
                   "r"((b)[0]), "r"((b)[1]))

// ============================================================================
// split-convert: fp32 -> (bf16 hi, bf16 lo = bf16(x - float(hi)))
// ============================================================================
__global__ void conv_split(const float* __restrict__ src,
                           __nv_bfloat16* __restrict__ dh,
                           __nv_bfloat16* __restrict__ dl, int n4) {
    int i = blockIdx.x * 256 + threadIdx.x;
    if (i >= n4) return;
    float4 v = *(const float4*)(src + (size_t)i * 4);
    __nv_bfloat16 h0 = __float2bfloat16(v.x);
    __nv_bfloat16 h1 = __float2bfloat16(v.y);
    __nv_bfloat16 h2 = __float2bfloat16(v.z);
    __nv_bfloat16 h3 = __float2bfloat16(v.w);
    __nv_bfloat162 ph0, ph1, pl0, pl1;
    ph0.x = h0; ph0.y = h1; ph1.x = h2; ph1.y = h3;
    pl0.x = __float2bfloat16(v.x - __bfloat162float(h0));
    pl0.y = __float2bfloat16(v.y - __bfloat162float(h1));
    pl1.x = __float2bfloat16(v.z - __bfloat162float(h2));
    pl1.y = __float2bfloat16(v.w - __bfloat162float(h3));
    *(__nv_bfloat162*)(dh + (size_t)i * 4)     = ph0;
    *(__nv_bfloat162*)(dh + (size_t)i * 4 + 2) = ph1;
    *(__nv_bfloat162*)(dl + (size_t)i * 4)     = pl0;
    *(__nv_bfloat162*)(dl + (size_t)i * 4 + 2) = pl1;
}

// ============================================================================
// HMMA input GEMM (unchanged from passing round 4/6/7)
// ============================================================================
#define KT       32
#define NKT      (DIN / KT)
#define TSTRB    80
#define TILE_SB  (128 * TSTRB)
#define STAGE_SB (4 * TILE_SB)
#define GEMM_SM  (2 * STAGE_SB)

__global__ __launch_bounds__(256)
void gemm_input_tc(const float* __restrict__ bu, const float* __restrict__ br,
                   const float* __restrict__ bc) {
    extern __shared__ char smem[];
    const uint32_t sm0 = smem_to_u32(smem);

    const int g  = blockIdx.z;
    const int n0 = blockIdx.x * 128;
    const int m0 = blockIdx.y * 128;
    const float* bias = (g == 0) ? bu : (g == 1) ? br : bc;
    float* X = g_X + (size_t)g * TBROWS * DH;

    const int tid  = threadIdx.x;
    const int lane = tid & 31;
    const int wm   = (tid >> 5) & 3;
    const int wn   = tid >> 7;

    const int p = tid >> 6;
    const int q = tid & 63;
    const __nv_bfloat16* srcb;
    if (p == 0)      srcb = g_Ah + (size_t)(m0 + q) * DIN;
    else if (p == 1) srcb = g_Al + (size_t)(m0 + q) * DIN;
    else if (p == 2) srcb = g_Bh + ((size_t)g * DH + n0 + q) * DIN;
    else             srcb = g_Bl + ((size_t)g * DH + n0 + q) * DIN;
    const uint32_t dstb = sm0 + p * TILE_SB + q * TSTRB;

    float acc[2][8][4];
#pragma unroll
    for (int mf = 0; mf < 2; mf++)
#pragma unroll
        for (int nf = 0; nf < 8; nf++)
#pragma unroll
            for (int e = 0; e < 4; e++) acc[mf][nf][e] = 0.f;

#pragma unroll
    for (int j = 0; j < 4; j++) {
        cp16(dstb + j * 16,               srcb + j * 8);
        cp16(dstb + 64 * TSTRB + j * 16,  srcb + (size_t)64 * DIN + j * 8);
    }
    CP_COMMIT();

    for (int c = 0; c < NKT; c++) {
        const uint32_t sb = sm0 + (c & 1) * STAGE_SB;
        if (c + 1 < NKT) {
            const uint32_t d2 = sm0 + ((c + 1) & 1) * STAGE_SB
                              + p * TILE_SB + q * TSTRB;
            const __nv_bfloat16* s2 = srcb + (c + 1) * KT;
#pragma unroll
            for (int j = 0; j < 4; j++) {
                cp16(d2 + j * 16,              s2 + j * 8);
                cp16(d2 + 64 * TSTRB + j * 16, s2 + (size_t)64 * DIN + j * 8);
            }
            CP_COMMIT();
            CP_WAIT(1);
        } else {
            CP_WAIT(0);
        }
        __syncthreads();

        const uint32_t arow = (lane & 15);
        const uint32_t acol = (lane >> 4) * 16;
#pragma unroll
        for (int s = 0; s < 2; s++) {
            uint32_t ah[2][4], al[2][4], bh[8][2], bl[8][2];
#pragma unroll
            for (int mf = 0; mf < 2; mf++) {
                uint32_t ra = sb + (32 * wm + 16 * mf + arow) * TSTRB + acol + s * 32;
                LDSM_X4(ah[mf][0], ah[mf][1], ah[mf][2], ah[mf][3], ra);
                LDSM_X4(al[mf][0], al[mf][1], al[mf][2], al[mf][3], ra + TILE_SB);
            }
#pragma unroll
            for (int nfp = 0; nfp < 4; nfp++) {
                uint32_t rb = sb + 2 * TILE_SB
                            + (64 * wn + 16 * nfp + arow) * TSTRB + acol + s * 32;
                uint32_t r0, r1, r2, r3;
                LDSM_X4(r0, r1, r2, r3, rb);
                bh[2 * nfp][0] = r0; bh[2 * nfp][1] = r2;
                bh[2 * nfp + 1][0] = r1; bh[2 * nfp + 1][1] = r3;
                LDSM_X4(r0, r1, r2, r3, rb + TILE_SB);
                bl[2 * nfp][0] = r0; bl[2 * nfp][1] = r2;
                bl[2 * nfp + 1][0] = r1; bl[2 * nfp + 1][1] = r3;
            }
#pragma unroll
            for (int mf = 0; mf < 2; mf++)
#pragma unroll
                for (int nf = 0; nf < 8; nf++) {
                    MMA_BF16(acc[mf][nf], ah[mf], bh[nf]);
                    MMA_BF16(acc[mf][nf], ah[mf], bl[nf]);
                    MMA_BF16(acc[mf][nf], al[mf], bh[nf]);
                }
        }
        __syncthreads();
    }

#pragma unroll
    for (int mf = 0; mf < 2; mf++) {
        int row0 = m0 + wm * 32 + mf * 16 + (lane >> 2);
#pragma unroll
        for (int nf = 0; nf < 8; nf++) {
            int col = n0 + wn * 64 + nf * 8 + (lane & 3) * 2;
            float2 bv = *(const float2*)(bias + col);
            float2 o0 = make_float2(acc[mf][nf][0] + bv.x, acc[mf][nf][1] + bv.y);
            float2 o1 = make_float2(acc[mf][nf][2] + bv.x, acc[mf][nf][3] + bv.y);
            *(float2*)(X + (size_t)row0 * DH + col)       = o0;
            *(float2*)(X + (size_t)(row0 + 8) * DH + col) = o1;
        }
    }
}

// ============================================================================
// Software grid barrier (monotonic; tight spin, no nanosleep)
// ============================================================================
__device__ __forceinline__ void grid_barrier(unsigned& lgen) {
    __syncthreads();
    if (threadIdx.x == 0) {
        unsigned target = ++lgen;
        __threadfence();
        unsigned arr = atomicAdd(&g_bar_count, 1u) + 1u;
        if (arr == target * NBLK) {
            __threadfence();
            g_bar_gen = target;
        } else {
            while (g_bar_gen < target) { }
        }
        __threadfence();
    }
    __syncthreads();
}

// ============================================================================
// init: h <- hx (fp32 + bf16 split), reset barrier state
// ============================================================================
__global__ void init_h(const float* __restrict__ hx) {
    int i = blockIdx.x * 256 + threadIdx.x;
    float v = hx[i];
    g_h[i] = v;
    __nv_bfloat16 hi = __float2bfloat16(v);
    g_hh[i] = hi;
    g_hl[i] = __float2bfloat16(v - __bfloat162float(hi));
    if (i == 0) { g_bar_count = 0u; g_bar_gen = 0u; }
}

// ============================================================================
// Persistent tensor-core recurrence, warp-autonomous k-streaming.
// Epilogue gmem operands are prefetched BEFORE each GEMM loop (barrier-stable
// values) so their DRAM/L2 latency hides behind the MMA work.
// ============================================================================
#define WSA_HALF 40960
#define WSB_HALF 20480
#define SM_WSA   0
#define SM_WSB   81920
#define SM_STG   122880
#define STG_WARP 12288
#define STG_STAGE 6144      // hi 3072 + lo 3072
#define PERS_SM  221184

// stage one 64-row x 16-k (hi,lo) slice into this warp's buffer (8 cp16/lane)
__device__ __forceinline__ void stage_slice(uint32_t dst,
                                            const __nv_bfloat16* __restrict__ hi,
                                            const __nv_bfloat16* __restrict__ lo,
                                            int kbase) {
    const int lane = threadIdx.x & 31;
#pragma unroll
    for (int rr = 0; rr < 2; rr++) {
        int row = lane + 32 * rr;
        const __nv_bfloat16* sh = hi + row * DH + kbase;
        const __nv_bfloat16* sl = lo + row * DH + kbase;
        uint32_t d = dst + row * 48;
        cp16(d,              sh);
        cp16(d + 16,         sh + 8);
        cp16(d + 3072,       sl);
        cp16(d + 3072 + 16,  sl + 8);
    }
}

__global__ __launch_bounds__(NTHR, 1)
void gru_pers_tc(const float* __restrict__ Wu, const float* __restrict__ Wr,
                 const float* __restrict__ Wc, float* __restrict__ out,
                 int write_tail) {
    extern __shared__ char sm[];
    const uint32_t sm0 = smem_to_u32(sm);
    float* red = (float*)(sm + SM_STG);   // per-warp regions, 3072 floats each

    const int tid  = threadIdx.x;
    const int wid  = tid >> 5;
    const int lane = tid & 31;
    const int b    = blockIdx.x;
    const int gA   = b >> 6;            // 0: update cols, 1: reset cols
    const int n0A  = (b & 63) * 16;
    const int n0B  = b * 8;
    const float* WA = gA ? Wr : Wu;

    // ---- one-time: split W_hh slices into smem (80B-stride ktile layout)
    for (int e = tid; e < 16 * 512; e += NTHR) {
        int row = e >> 9, k = (e & 511) * 2;
        float2 v = *(const float2*)(WA + (size_t)(n0A + row) * DH + k);
        __nv_bfloat162 hi2, lo2;
        hi2.x = __float2bfloat16(v.x); hi2.y = __float2bfloat16(v.y);
        lo2.x = __float2bfloat16(v.x - __bfloat162float(hi2.x));
        lo2.y = __float2bfloat16(v.y - __bfloat162float(hi2.y));
        uint32_t ad = SM_WSA + (k >> 5) * 1280 + row * 80 + (k & 31) * 2;
        *(__nv_bfloat162*)(sm + ad)            = hi2;
        *(__nv_bfloat162*)(sm + ad + WSA_HALF) = lo2;
    }
    for (int e = tid; e < 8 * 512; e += NTHR) {
        int row = e >> 9, k = (e & 511) * 2;
        float2 v = *(const float2*)(Wc + (size_t)(n0B + row) * DH + k);
        __nv_bfloat162 hi2, lo2;
        hi2.x = __float2bfloat16(v.x); hi2.y = __float2bfloat16(v.y);
        lo2.x = __float2bfloat16(v.x - __bfloat162float(hi2.x));
        lo2.y = __float2bfloat16(v.y - __bfloat162float(hi2.y));
        uint32_t ad = SM_WSB + (k >> 5) * 640 + row * 80 + (k & 31) * 2;
        *(__nv_bfloat162*)(sm + ad)            = hi2;
        *(__nv_bfloat162*)(sm + ad + WSB_HALF) = lo2;
    }
    __syncthreads();

    const uint32_t my_stg = sm0 + SM_STG + wid * STG_WARP;
    const int kw = 128 * wid;           // warp's k base
    // epilogue operand indices (fixed per thread)
    const int mE  = tid >> 2;
    const int cbA = (tid & 3) * 4;
    const int nAe = n0A + cbA;
    const int cbB = (tid & 3) * 2;
    const int nBe = n0B + cbB;
    unsigned lgen = 0;

    for (int t = 0; t < T_STEPS; t++) {
        // ======================= PHASE A (u, r) =======================
        // prefetch epilogue operands (barrier-stable this step)
        float4 xgA = *(const float4*)(g_X + ((size_t)gA * TBROWS
                          + (size_t)t * B_SZ) * DH + mE * DH + nAe);
        float4 hvA = *(const float4*)(g_h + mE * DH + nAe);

        float acc[4][2][4];
#pragma unroll
        for (int mf = 0; mf < 4; mf++)
#pragma unroll
            for (int nf = 0; nf < 2; nf++)
#pragma unroll
                for (int e = 0; e < 4; e++) acc[mf][nf][e] = 0.f;

        stage_slice(my_stg, g_hh, g_hl, kw);
        CP_COMMIT();

#pragma unroll
        for (int j = 0; j < 8; j++) {
            if (j < 7) {
                stage_slice(my_stg + ((j + 1) & 1) * STG_STAGE, g_hh, g_hl,
                            kw + 16 * (j + 1));
                CP_COMMIT();
                CP_WAIT(1);
            } else {
                CP_WAIT(0);
            }
            __syncwarp();

            const int kt = 4 * wid + (j >> 1);
            uint32_t bA = sm0 + SM_WSA + kt * 1280
                        + (lane & 15) * 80 + (lane >> 4) * 16 + (j & 1) * 32;
            uint32_t r0, r1, r2, r3;
            uint32_t bh0[2], bh1[2], bl0[2], bl1[2];
            LDSM_X4(r0, r1, r2, r3, bA);
            bh0[0] = r0; bh0[1] = r2; bh1[0] = r1; bh1[1] = r3;
            LDSM_X4(r0, r1, r2, r3, bA + WSA_HALF);
            bl0[0] = r0; bl0[1] = r2; bl1[0] = r1; bl1[1] = r3;
            const uint32_t ab = my_stg + (j & 1) * STG_STAGE;
#pragma unroll
            for (int mf = 0; mf < 4; mf++) {
                uint32_t ra = ab + (mf * 16 + (lane & 15)) * 48 + (lane >> 4) * 16;
                uint32_t ah[4], al[4];
                LDSM_X4(ah[0], ah[1], ah[2], ah[3], ra);
                LDSM_X4(al[0], al[1], al[2], al[3], ra + 3072);
                MMA_BF16(acc[mf][0], ah, bh0);
                MMA_BF16(acc[mf][0], ah, bl0);
                MMA_BF16(acc[mf][0], al, bh0);
                MMA_BF16(acc[mf][1], ah, bh1);
                MMA_BF16(acc[mf][1], ah, bl1);
                MMA_BF16(acc[mf][1], al, bh1);
            }
        }

        // ---- per-warp partials into own region, then cross-warp reduce
        {
            float* rw = red + wid * 3072;
#pragma unroll
            for (int mf = 0; mf < 4; mf++)
#pragma unroll
                for (int nf = 0; nf < 2; nf++) {
                    int row = mf * 16 + (lane >> 2);
                    int col = nf * 8 + (lane & 3) * 2;
                    *(float2*)&rw[row * 20 + col] =
                        make_float2(acc[mf][nf][0], acc[mf][nf][1]);
                    *(float2*)&rw[(row + 8) * 20 + col] =
                        make_float2(acc[mf][nf][2], acc[mf][nf][3]);
                }
        }
        __syncthreads();
        {
            float4 sv = make_float4(0.f, 0.f, 0.f, 0.f);
#pragma unroll
            for (int w = 0; w < 8; w++) {
                float4 v = *(float4*)&red[w * 3072 + mE * 20 + cbA];
                sv.x += v.x; sv.y += v.y; sv.z += v.z; sv.w += v.w;
            }
            float s0 = 1.f / (1.f + expf(-(sv.x + xgA.x)));
            float s1 = 1.f / (1.f + expf(-(sv.y + xgA.y)));
            float s2 = 1.f / (1.f + expf(-(sv.z + xgA.z)));
            float s3 = 1.f / (1.f + expf(-(sv.w + xgA.w)));
            if (gA == 0) {
                *(float4*)&g_u[mE * DH + nAe] = make_float4(s0, s1, s2, s3);
            } else {
                float r0f = s0 * hvA.x, r1f = s1 * hvA.y;
                float r2f = s2 * hvA.z, r3f = s3 * hvA.w;
                __nv_bfloat162 h01, h23, l01, l23;
                h01.x = __float2bfloat16(r0f); h01.y = __float2bfloat16(r1f);
                h23.x = __float2bfloat16(r2f); h23.y = __float2bfloat16(r3f);
                l01.x = __float2bfloat16(r0f - __bfloat162float(h01.x));
                l01.y = __float2bfloat16(r1f - __bfloat162float(h01.y));
                l23.x = __float2bfloat16(r2f - __bfloat162float(h23.x));
                l23.y = __float2bfloat16(r3f - __bfloat162float(h23.y));
                *(__nv_bfloat162*)&g_rhh[mE * DH + nAe]     = h01;
                *(__nv_bfloat162*)&g_rhh[mE * DH + nAe + 2] = h23;
                *(__nv_bfloat162*)&g_rhl[mE * DH + nAe]     = l01;
                *(__nv_bfloat162*)&g_rhl[mE * DH + nAe + 2] = l23;
            }
        }
        grid_barrier(lgen);

        // ======================= PHASE B (candidate + update) =============
        // prefetch epilogue operands (u/h frozen once phase B starts)
        float2 xcB = *(const float2*)(g_X + (2ull * TBROWS
                          + (size_t)t * B_SZ) * DH + mE * DH + nBe);
        float2 uvB = *(const float2*)(g_u + mE * DH + nBe);
        float2 hvB = *(const float2*)(g_h + mE * DH + nBe);

        float accB[4][4];
#pragma unroll
        for (int mf = 0; mf < 4; mf++)
#pragma unroll
            for (int e = 0; e < 4; e++) accB[mf][e] = 0.f;

        stage_slice(my_stg, g_rhh, g_rhl, kw);
        CP_COMMIT();

#pragma unroll
        for (int j = 0; j < 8; j++) {
            if (j < 7) {
                stage_slice(my_stg + ((j + 1) & 1) * STG_STAGE, g_rhh, g_rhl,
                            kw + 16 * (j + 1));
                CP_COMMIT();
                CP_WAIT(1);
            } else {
                CP_WAIT(0);
            }
            __syncwarp();

            const int kt = 4 * wid + (j >> 1);
            const int s  = j & 1;
            uint32_t bB = sm0 + SM_WSB + kt * 640
                        + (lane & 7) * 80 + (lane >> 3) * 16;
            uint32_t r0, r1, r2, r3;
            uint32_t bh[2], bl[2];
            LDSM_X4(r0, r1, r2, r3, bB);
            if (s == 0) { bh[0] = r0; bh[1] = r1; } else { bh[0] = r2; bh[1] = r3; }
            LDSM_X4(r0, r1, r2, r3, bB + WSB_HALF);
            if (s == 0) { bl[0] = r0; bl[1] = r1; } else { bl[0] = r2; bl[1] = r3; }
            const uint32_t ab = my_stg + (j & 1) * STG_STAGE;
#pragma unroll
            for (int mf = 0; mf < 4; mf++) {
                uint32_t ra = ab + (mf * 16 + (lane & 15)) * 48 + (lane >> 4) * 16;
                uint32_t ah[4], al[4];
                LDSM_X4(ah[0], ah[1], ah[2], ah[3], ra);
                LDSM_X4(al[0], al[1], al[2], al[3], ra + 3072);
                MMA_BF16(accB[mf], ah, bh);
                MMA_BF16(accB[mf], ah, bl);
                MMA_BF16(accB[mf], al, bh);
            }
        }

        // ---- reduction (8 partials of 64x8)
        {
            float* rw = red + wid * 3072;
#pragma unroll
            for (int mf = 0; mf < 4; mf++) {
                int row = mf * 16 + (lane >> 2);
                int col = (lane & 3) * 2;
                *(float2*)&rw[row * 10 + col] =
                    make_float2(accB[mf][0], accB[mf][1]);
                *(float2*)&rw[(row + 8) * 10 + col] =
                    make_float2(accB[mf][2], accB[mf][3]);
            }
        }
        __syncthreads();
        {
            float2 sv = make_float2(0.f, 0.f);
#pragma unroll
            for (int w = 0; w < 8; w++) {
                float2 v = *(float2*)&red[w * 3072 + mE * 10 + cbB];
                sv.x += v.x; sv.y += v.y;
            }
            float c0 = tanhf(sv.x + xcB.x);
            float c1 = tanhf(sv.y + xcB.y);
            float hn0 = (1.f - uvB.x) * hvB.x + uvB.x * c0;
            float hn1 = (1.f - uvB.y) * hvB.y + uvB.y * c1;
            *(float2*)&g_h[mE * DH + nBe] = make_float2(hn0, hn1);
            __nv_bfloat162 hh2, hl2;
            hh2.x = __float2bfloat16(hn0); hh2.y = __float2bfloat16(hn1);
            hl2.x = __float2bfloat16(hn0 - __bfloat162float(hh2.x));
            hl2.y = __float2bfloat16(hn1 - __bfloat162float(hh2.y));
            *(__nv_bfloat162*)&g_hh[mE * DH + nBe] = hh2;
            *(__nv_bfloat162*)&g_hl[mE * DH + nBe] = hl2;
            size_t ob = ((size_t)t * B_SZ + mE) * DH + nBe;
            *(float2*)&out[ob] = make_float2(hn0, hn1);
            if (write_tail && t == T_STEPS - 1) {
                size_t tb = ((size_t)T_STEPS * B_SZ + mE) * DH + nBe;
                *(float2*)&out[tb] = make_float2(hn0, hn1);
            }
        }
        grid_barrier(lgen);
    }
}

// ============================================================================
// Launch
// ============================================================================
extern "C" void kernel_launch(void* const* d_in, const int* in_sizes, int n_in,
                              void* d_out, int out_size) {
    const float* emb    = (const float*)d_in[0];
    const float* hx     = (const float*)d_in[1];
    const float* w_ih_u = (const float*)d_in[2];
    const float* w_ih_r = (const float*)d_in[3];
    const float* w_ih_c = (const float*)d_in[4];
    const float* w_hh_u = (const float*)d_in[5];
    const float* w_hh_r = (const float*)d_in[6];
    const float* w_hh_c = (const float*)d_in[7];
    const float* b_u    = (const float*)d_in[8];
    const float* b_r    = (const float*)d_in[9];
    const float* b_c    = (const float*)d_in[10];
    float* out = (float*)d_out;

    const long long main_elems = (long long)T_STEPS * B_SZ * DH;
    int write_tail = ((long long)out_size >= main_elems + (long long)B_SZ * DH) ? 1 : 0;

    cudaFuncSetAttribute(gemm_input_tc,
                         cudaFuncAttributeMaxDynamicSharedMemorySize, GEMM_SM);
    cudaFuncSetAttribute(gru_pers_tc,
                         cudaFuncAttributeMaxDynamicSharedMemorySize, PERS_SM);

    __nv_bfloat16 *pAh, *pAl, *pBh, *pBl;
    cudaGetSymbolAddress((void**)&pAh, g_Ah);
    cudaGetSymbolAddress((void**)&pAl, g_Al);
    cudaGetSymbolAddress((void**)&pBh, g_Bh);
    cudaGetSymbolAddress((void**)&pBl, g_Bl);

    {
        int n4 = TBROWS * DIN / 4;
        conv_split<<<(n4 + 255) / 256, 256>>>(emb, pAh, pAl, n4);
        int w4 = DH * DIN / 4;
        conv_split<<<(w4 + 255) / 256, 256>>>(w_ih_u, pBh, pBl, w4);
        conv_split<<<(w4 + 255) / 256, 256>>>(w_ih_r, pBh + (size_t)DH * DIN,
                                              pBl + (size_t)DH * DIN, w4);
        conv_split<<<(w4 + 255) / 256, 256>>>(w_ih_c, pBh + 2ull * DH * DIN,
                                              pBl + 2ull * DH * DIN, w4);
    }

    dim3 g1(DH / 128, TBROWS / 128, 3);
    gemm_input_tc<<<g1, 256, GEMM_SM>>>(b_u, b_r, b_c);
    init_h<<<(B_SZ * DH) / 256, 256>>>(hx);
    gru_pers_tc<<<NBLK, NTHR, PERS_SM>>>(w_hh_u, w_hh_r, w_hh_c, out, write_tail);
}

// round 9
// speedup vs baseline: 1.6471x; 1.0065x over previous
#include <cuda_runtime.h>
#include <cuda_bf16.h>
#include <math.h>
#include <stdint.h>

#define T_STEPS 512
#define B_SZ    64
#define DIN     1024
#define DH      1024
#define TBROWS  (T_STEPS * B_SZ)   // 32768

#define NBLK 128
#define NTHR 256

// ---------------- device scratch (static; no allocation allowed) -------------
__device__ float g_X[3ull * TBROWS * DH];            // x@Wih^T + b, per gate
__device__ __nv_bfloat16 g_Ah[(size_t)TBROWS * DIN]; // emb split hi
__device__ __nv_bfloat16 g_Al[(size_t)TBROWS * DIN]; // emb split lo
__device__ __nv_bfloat16 g_Bh[3ull * DH * DIN];      // w_ih split hi (3 gates)
__device__ __nv_bfloat16 g_Bl[3ull * DH * DIN];      // w_ih split lo
__device__ float g_h [B_SZ * DH];                    // hidden state fp32
__device__ float g_u [B_SZ * DH];                    // update gate
__device__ __nv_bfloat16 g_hh [B_SZ * DH];           // h split hi
__device__ __nv_bfloat16 g_hl [B_SZ * DH];           // h split lo
__device__ __nv_bfloat16 g_rhh[B_SZ * DH];           // (r*h) split hi
__device__ __nv_bfloat16 g_rhl[B_SZ * DH];           // (r*h) split lo
__device__ volatile unsigned g_flags[NBLK * 8];      // per-CTA arrival flags (padded)
__device__ volatile unsigned g_bar_gen;              // release word

// ============================================================================
// helpers
// ============================================================================
__device__ __forceinline__ uint32_t smem_to_u32(const void* p) {
    uint32_t a;
    asm("{ .reg .u64 t; cvta.to.shared.u64 t, %1; cvt.u32.u64 %0, t; }"
        : "=r"(a) : "l"(p));
    return a;
}
__device__ __forceinline__ void cp16(uint32_t dst, const void* src) {
    asm volatile("cp.async.cg.shared.global [%0], [%1], 16;"
                 :: "r"(dst), "l"(src));
}
#define CP_COMMIT() asm volatile("cp.async.commit_group;" ::: "memory")
#define CP_WAIT(n)  asm volatile("cp.async.wait_group %0;" :: "n"(n) : "memory")

#define LDSM_X4(r0, r1, r2, r3, addr) \
    asm volatile("ldmatrix.sync.aligned.m8n8.x4.shared.b16 {%0,%1,%2,%3}, [%4];" \
                 : "=r"(r0), "=r"(r1), "=r"(r2), "=r"(r3) : "r"(addr))

#define MMA_BF16(d, a, b) \
    asm volatile("mma.sync.aligned.m16n8k16.row.col.f32.bf16.bf16.f32 " \
                 "{%0,%1,%2,%3}, {%4,%5,%6,%7}, {%8,%9}, {%0,%1,%2,%3};" \
                 : "+f"((d)[0]), "+f"((d)[1]), "+f"((d)[2]), "+f"((d)[3]) \
                 : "r"((a)[0]), "r"((a)[1]), "r"((a)[2]), "r"((a)[3]), \
                   "r"((b)[0]), "r"((b)[1]))

// ============================================================================
// prep_all: split-convert emb + 3 input weights, init h (fp32 + bf16 split),
// reset barrier state. ONE launch (keeps total launches/call at 3 so ncu's
// -s 5 -c 1 lands on gru_pers_tc).
// ============================================================================
__device__ __forceinline__ void split4(const float* __restrict__ src,
                                       __nv_bfloat16* __restrict__ dh,
                                       __nv_bfloat16* __restrict__ dl, size_t i) {
    float4 v = *(const float4*)(src + i * 4);
    __nv_bfloat16 h0 = __float2bfloat16(v.x);
    __nv_bfloat16 h1 = __float2bfloat16(v.y);
    __nv_bfloat16 h2 = __float2bfloat16(v.z);
    __nv_bfloat16 h3 = __float2bfloat16(v.w);
    __nv_bfloat162 ph0, ph1, pl0, pl1;
    ph0.x = h0; ph0.y = h1; ph1.x = h2; ph1.y = h3;
    pl0.x = __float2bfloat16(v.x - __bfloat162float(h0));
    pl0.y = __float2bfloat16(v.y - __bfloat162float(h1));
    pl1.x = __float2bfloat16(v.z - __bfloat162float(h2));
    pl1.y = __float2bfloat16(v.w - __bfloat162float(h3));
    *(__nv_bfloat162*)(dh + i * 4)     = ph0;
    *(__nv_bfloat162*)(dh + i * 4 + 2) = ph1;
    *(__nv_bfloat162*)(dl + i * 4)     = pl0;
    *(__nv_bfloat162*)(dl + i * 4 + 2) = pl1;
}

#define E4 ((size_t)TBROWS * DIN / 4)   // 8388608
#define W4 ((size_t)DH * DIN / 4)       // 262144
#define H4 ((size_t)B_SZ * DH / 4)      // 16384
#define PREP_TOT (E4 + 3 * W4 + H4)

__global__ void prep_all(const float* __restrict__ emb,
                         const float* __restrict__ wu,
                         const float* __restrict__ wr,
                         const float* __restrict__ wc,
                         const float* __restrict__ hx) {
    size_t i = (size_t)blockIdx.x * 256 + threadIdx.x;
    if (i >= PREP_TOT) return;
    if (i < E4) { split4(emb, g_Ah, g_Al, i); return; }
    i -= E4;
    if (i < W4) { split4(wu, g_Bh, g_Bl, i); return; }
    i -= W4;
    if (i < W4) { split4(wr, g_Bh + (size_t)DH * DIN, g_Bl + (size_t)DH * DIN, i); return; }
    i -= W4;
    if (i < W4) { split4(wc, g_Bh + 2ull * DH * DIN, g_Bl + 2ull * DH * DIN, i); return; }
    i -= W4;
    {
        float4 v = *(const float4*)(hx + i * 4);
        *(float4*)(g_h + i * 4) = v;
        __nv_bfloat162 hh0, hh1, hl0, hl1;
        hh0.x = __float2bfloat16(v.x); hh0.y = __float2bfloat16(v.y);
        hh1.x = __float2bfloat16(v.z); hh1.y = __float2bfloat16(v.w);
        hl0.x = __float2bfloat16(v.x - __bfloat162float(hh0.x));
        hl0.y = __float2bfloat16(v.y - __bfloat162float(hh0.y));
        hl1.x = __float2bfloat16(v.z - __bfloat162float(hh1.x));
        hl1.y = __float2bfloat16(v.w - __bfloat162float(hh1.y));
        *(__nv_bfloat162*)(g_hh + i * 4)     = hh0;
        *(__nv_bfloat162*)(g_hh + i * 4 + 2) = hh1;
        *(__nv_bfloat162*)(g_hl + i * 4)     = hl0;
        *(__nv_bfloat162*)(g_hl + i * 4 + 2) = hl1;
        if (i < NBLK * 8) g_flags[i] = 0u;
        if (i == 0) g_bar_gen = 0u;
    }
}

// ============================================================================
// HMMA input GEMM (unchanged from passing rounds 4-8)
// ============================================================================
#define KT       32
#define NKT      (DIN / KT)
#define TSTRB    80
#define TILE_SB  (128 * TSTRB)
#define STAGE_SB (4 * TILE_SB)
#define GEMM_SM  (2 * STAGE_SB)

__global__ __launch_bounds__(256)
void gemm_input_tc(const float* __restrict__ bu, const float* __restrict__ br,
                   const float* __restrict__ bc) {
    extern __shared__ char smem[];
    const uint32_t sm0 = smem_to_u32(smem);

    const int g  = blockIdx.z;
    const int n0 = blockIdx.x * 128;
    const int m0 = blockIdx.y * 128;
    const float* bias = (g == 0) ? bu : (g == 1) ? br : bc;
    float* X = g_X + (size_t)g * TBROWS * DH;

    const int tid  = threadIdx.x;
    const int lane = tid & 31;
    const int wm   = (tid >> 5) & 3;
    const int wn   = tid >> 7;

    const int p = tid >> 6;
    const int q = tid & 63;
    const __nv_bfloat16* srcb;
    if (p == 0)      srcb = g_Ah + (size_t)(m0 + q) * DIN;
    else if (p == 1) srcb = g_Al + (size_t)(m0 + q) * DIN;
    else if (p == 2) srcb = g_Bh + ((size_t)g * DH + n0 + q) * DIN;
    else             srcb = g_Bl + ((size_t)g * DH + n0 + q) * DIN;
    const uint32_t dstb = sm0 + p * TILE_SB + q * TSTRB;

    float acc[2][8][4];
#pragma unroll
    for (int mf = 0; mf < 2; mf++)
#pragma unroll
        for (int nf = 0; nf < 8; nf++)
#pragma unroll
            for (int e = 0; e < 4; e++) acc[mf][nf][e] = 0.f;

#pragma unroll
    for (int j = 0; j < 4; j++) {
        cp16(dstb + j * 16,               srcb + j * 8);
        cp16(dstb + 64 * TSTRB + j * 16,  srcb + (size_t)64 * DIN + j * 8);
    }
    CP_COMMIT();

    for (int c = 0; c < NKT; c++) {
        const uint32_t sb = sm0 + (c & 1) * STAGE_SB;
        if (c + 1 < NKT) {
            const uint32_t d2 = sm0 + ((c + 1) & 1) * STAGE_SB
                              + p * TILE_SB + q * TSTRB;
            const __nv_bfloat16* s2 = srcb + (c + 1) * KT;
#pragma unroll
            for (int j = 0; j < 4; j++) {
                cp16(d2 + j * 16,              s2 + j * 8);
                cp16(d2 + 64 * TSTRB + j * 16, s2 + (size_t)64 * DIN + j * 8);
            }
            CP_COMMIT();
            CP_WAIT(1);
        } else {
            CP_WAIT(0);
        }
        __syncthreads();

        const uint32_t arow = (lane & 15);
        const uint32_t acol = (lane >> 4) * 16;
#pragma unroll
        for (int s = 0; s < 2; s++) {
            uint32_t ah[2][4], al[2][4], bh[8][2], bl[8][2];
#pragma unroll
            for (int mf = 0; mf < 2; mf++) {
                uint32_t ra = sb + (32 * wm + 16 * mf + arow) * TSTRB + acol + s * 32;
                LDSM_X4(ah[mf][0], ah[mf][1], ah[mf][2], ah[mf][3], ra);
                LDSM_X4(al[mf][0], al[mf][1], al[mf][2], al[mf][3], ra + TILE_SB);
            }
#pragma unroll
            for (int nfp = 0; nfp < 4; nfp++) {
                uint32_t rb = sb + 2 * TILE_SB
                            + (64 * wn + 16 * nfp + arow) * TSTRB + acol + s * 32;
                uint32_t r0, r1, r2, r3;
                LDSM_X4(r0, r1, r2, r3, rb);
                bh[2 * nfp][0] = r0; bh[2 * nfp][1] = r2;
                bh[2 * nfp + 1][0] = r1; bh[2 * nfp + 1][1] = r3;
                LDSM_X4(r0, r1, r2, r3, rb + TILE_SB);
                bl[2 * nfp][0] = r0; bl[2 * nfp][1] = r2;
                bl[2 * nfp + 1][0] = r1; bl[2 * nfp + 1][1] = r3;
            }
#pragma unroll
            for (int mf = 0; mf < 2; mf++)
#pragma unroll
                for (int nf = 0; nf < 8; nf++) {
                    MMA_BF16(acc[mf][nf], ah[mf], bh[nf]);
                    MMA_BF16(acc[mf][nf], ah[mf], bl[nf]);
                    MMA_BF16(acc[mf][nf], al[mf], bh[nf]);
                }
        }
        __syncthreads();
    }

#pragma unroll
    for (int mf = 0; mf < 2; mf++) {
        int row0 = m0 + wm * 32 + mf * 16 + (lane >> 2);
#pragma unroll
        for (int nf = 0; nf < 8; nf++) {
            int col = n0 + wn * 64 + nf * 8 + (lane & 3) * 2;
            float2 bv = *(const float2*)(bias + col);
            float2 o0 = make_float2(acc[mf][nf][0] + bv.x, acc[mf][nf][1] + bv.y);
            float2 o1 = make_float2(acc[mf][nf][2] + bv.x, acc[mf][nf][3] + bv.y);
            *(float2*)(X + (size_t)row0 * DH + col)       = o0;
            *(float2*)(X + (size_t)(row0 + 8) * DH + col) = o1;
        }
    }
}

// ============================================================================
// Atomic-free two-level grid barrier.
// Arrival: each CTA's thread 0 stores its flag (parallel, padded lines).
// CTA 0's first NBLK threads poll all flags, then publish the release word.
// ============================================================================
__device__ __forceinline__ void grid_barrier(unsigned& lgen) {
    __syncthreads();
    const unsigned target = ++lgen;
    if (threadIdx.x == 0) {
        __threadfence();
        g_flags[blockIdx.x * 8] = target;
    }
    if (blockIdx.x == 0) {
        if (threadIdx.x < NBLK) {
            while (g_flags[threadIdx.x * 8] < target) { }
        }
        __syncthreads();
        if (threadIdx.x == 0) {
            __threadfence();
            g_bar_gen = target;
        }
    }
    if (threadIdx.x == 0) {
        while (g_bar_gen < target) { }
        __threadfence();
    }
    __syncthreads();
}

// ============================================================================
// Persistent tensor-core recurrence (warp-autonomous k-streaming).
// ============================================================================
#define WSA_HALF 40960
#define WSB_HALF 20480
#define SM_WSA   0
#define SM_WSB   81920
#define SM_STG   122880
#define STG_WARP 12288
#define STG_STAGE 6144      // hi 3072 + lo 3072
#define PERS_SM  221184

__device__ __forceinline__ void stage_slice(uint32_t dst,
                                            const __nv_bfloat16* __restrict__ hi,
                                            const __nv_bfloat16* __restrict__ lo,
                                            int kbase) {
    const int lane = threadIdx.x & 31;
#pragma unroll
    for (int rr = 0; rr < 2; rr++) {
        int row = lane + 32 * rr;
        const __nv_bfloat16* sh = hi + row * DH + kbase;
        const __nv_bfloat16* sl = lo + row * DH + kbase;
        uint32_t d = dst + row * 48;
        cp16(d,              sh);
        cp16(d + 16,         sh + 8);
        cp16(d + 3072,       sl);
        cp16(d + 3072 + 16,  sl + 8);
    }
}

__global__ __launch_bounds__(NTHR, 1)
void gru_pers_tc(const float* __restrict__ Wu, const float* __restrict__ Wr,
                 const float* __restrict__ Wc, float* __restrict__ out,
                 int write_tail) {
    extern __shared__ char sm[];
    const uint32_t sm0 = smem_to_u32(sm);
    float* red = (float*)(sm + SM_STG);   // per-warp regions, 3072 floats each

    const int tid  = threadIdx.x;
    const int wid  = tid >> 5;
    const int lane = tid & 31;
    const int b    = blockIdx.x;
    const int gA   = b >> 6;            // 0: update cols, 1: reset cols
    const int n0A  = (b & 63) * 16;
    const int n0B  = b * 8;
    const float* WA = gA ? Wr : Wu;

    // ---- one-time: split W_hh slices into smem (80B-stride ktile layout)
    for (int e = tid; e < 16 * 512; e += NTHR) {
        int row = e >> 9, k = (e & 511) * 2;
        float2 v = *(const float2*)(WA + (size_t)(n0A + row) * DH + k);
        __nv_bfloat162 hi2, lo2;
        hi2.x = __float2bfloat16(v.x); hi2.y = __float2bfloat16(v.y);
        lo2.x = __float2bfloat16(v.x - __bfloat162float(hi2.x));
        lo2.y = __float2bfloat16(v.y - __bfloat162float(hi2.y));
        uint32_t ad = SM_WSA + (k >> 5) * 1280 + row * 80 + (k & 31) * 2;
        *(__nv_bfloat162*)(sm + ad)            = hi2;
        *(__nv_bfloat162*)(sm + ad + WSA_HALF) = lo2;
    }
    for (int e = tid; e < 8 * 512; e += NTHR) {
        int row = e >> 9, k = (e & 511) * 2;
        float2 v = *(const float2*)(Wc + (size_t)(n0B + row) * DH + k);
        __nv_bfloat162 hi2, lo2;
        hi2.x = __float2bfloat16(v.x); hi2.y = __float2bfloat16(v.y);
        lo2.x = __float2bfloat16(v.x - __bfloat162float(hi2.x));
        lo2.y = __float2bfloat16(v.y - __bfloat162float(hi2.y));
        uint32_t ad = SM_WSB + (k >> 5) * 640 + row * 80 + (k & 31) * 2;
        *(__nv_bfloat162*)(sm + ad)            = hi2;
        *(__nv_bfloat162*)(sm + ad + WSB_HALF) = lo2;
    }
    __syncthreads();

    const uint32_t my_stg = sm0 + SM_STG + wid * STG_WARP;
    const int kw = 128 * wid;           // warp's k base
    const int mE  = tid >> 2;
    const int cbA = (tid & 3) * 4;
    const int nAe = n0A + cbA;
    const int cbB = (tid & 3) * 2;
    const int nBe = n0B + cbB;
    unsigned lgen = 0;

    // register-carried h at (mE, nBe) — this thread both writes and reads it
    float hcar0, hcar1;
    { float2 hv = *(const float2*)(g_h + mE * DH + nBe); hcar0 = hv.x; hcar1 = hv.y; }
    // prefetch phase-A epilogue X for t=0
    float4 xgA = *(const float4*)(g_X + ((size_t)gA * TBROWS) * DH + mE * DH + nAe);

    for (int t = 0; t < T_STEPS; t++) {
        // ======================= PHASE A (u, r) =======================
        float4 hvA = *(const float4*)(g_h + mE * DH + nAe);

        float acc[4][2][4];
#pragma unroll
        for (int mf = 0; mf < 4; mf++)
#pragma unroll
            for (int nf = 0; nf < 2; nf++)
#pragma unroll
                for (int e = 0; e < 4; e++) acc[mf][nf][e] = 0.f;

        stage_slice(my_stg, g_hh, g_hl, kw);
        CP_COMMIT();

#pragma unroll
        for (int j = 0; j < 8; j++) {
            if (j < 7) {
                stage_slice(my_stg + ((j + 1) & 1) * STG_STAGE, g_hh, g_hl,
                            kw + 16 * (j + 1));
                CP_COMMIT();
                CP_WAIT(1);
            } else {
                CP_WAIT(0);
            }
            __syncwarp();

            const int kt = 4 * wid + (j >> 1);
            uint32_t bA = sm0 + SM_WSA + kt * 1280
                        + (lane & 15) * 80 + (lane >> 4) * 16 + (j & 1) * 32;
            uint32_t r0, r1, r2, r3;
            uint32_t bh0[2], bh1[2], bl0[2], bl1[2];
            LDSM_X4(r0, r1, r2, r3, bA);
            bh0[0] = r0; bh0[1] = r2; bh1[0] = r1; bh1[1] = r3;
            LDSM_X4(r0, r1, r2, r3, bA + WSA_HALF);
            bl0[0] = r0; bl0[1] = r2; bl1[0] = r1; bl1[1] = r3;
            const uint32_t ab = my_stg + (j & 1) * STG_STAGE;
#pragma unroll
            for (int mf = 0; mf < 4; mf++) {
                uint32_t ra = ab + (mf * 16 + (lane & 15)) * 48 + (lane >> 4) * 16;
                uint32_t ah[4], al[4];
                LDSM_X4(ah[0], ah[1], ah[2], ah[3], ra);
                LDSM_X4(al[0], al[1], al[2], al[3], ra + 3072);
                MMA_BF16(acc[mf][0], ah, bh0);
                MMA_BF16(acc[mf][0], ah, bl0);
                MMA_BF16(acc[mf][0], al, bh0);
                MMA_BF16(acc[mf][1], ah, bh1);
                MMA_BF16(acc[mf][1], ah, bl1);
                MMA_BF16(acc[mf][1], al, bh1);
            }
        }

        // ---- per-warp partials, cross-warp reduce, gate epilogue
        {
            float* rw = red + wid * 3072;
#pragma unroll
            for (int mf = 0; mf < 4; mf++)
#pragma unroll
                for (int nf = 0; nf < 2; nf++) {
                    int row = mf * 16 + (lane >> 2);
                    int col = nf * 8 + (lane & 3) * 2;
                    *(float2*)&rw[row * 20 + col] =
                        make_float2(acc[mf][nf][0], acc[mf][nf][1]);
                    *(float2*)&rw[(row + 8) * 20 + col] =
                        make_float2(acc[mf][nf][2], acc[mf][nf][3]);
                }
        }
        __syncthreads();
        {
            float4 sv = make_float4(0.f, 0.f, 0.f, 0.f);
#pragma unroll
            for (int w = 0; w < 8; w++) {
                float4 v = *(float4*)&red[w * 3072 + mE * 20 + cbA];
                sv.x += v.x; sv.y += v.y; sv.z += v.z; sv.w += v.w;
            }
            float s0 = 1.f / (1.f + expf(-(sv.x + xgA.x)));
            float s1 = 1.f / (1.f + expf(-(sv.y + xgA.y)));
            float s2 = 1.f / (1.f + expf(-(sv.z + xgA.z)));
            float s3 = 1.f / (1.f + expf(-(sv.w + xgA.w)));
            if (gA == 0) {
                *(float4*)&g_u[mE * DH + nAe] = make_float4(s0, s1, s2, s3);
            } else {
                float r0f = s0 * hvA.x, r1f = s1 * hvA.y;
                float r2f = s2 * hvA.z, r3f = s3 * hvA.w;
                __nv_bfloat162 h01, h23, l01, l23;
                h01.x = __float2bfloat16(r0f); h01.y = __float2bfloat16(r1f);
                h23.x = __float2bfloat16(r2f); h23.y = __float2bfloat16(r3f);
                l01.x = __float2bfloat16(r0f - __bfloat162float(h01.x));
                l01.y = __float2bfloat16(r1f - __bfloat162float(h01.y));
                l23.x = __float2bfloat16(r2f - __bfloat162float(h23.x));
                l23.y = __float2bfloat16(r3f - __bfloat162float(h23.y));
                *(__nv_bfloat162*)&g_rhh[mE * DH + nAe]     = h01;
                *(__nv_bfloat162*)&g_rhh[mE * DH + nAe + 2] = h23;
                *(__nv_bfloat162*)&g_rhl[mE * DH + nAe]     = l01;
                *(__nv_bfloat162*)&g_rhl[mE * DH + nAe + 2] = l23;
            }
        }
        // prefetch phase-B X (depends only on t) BEFORE the barrier
        float2 xcB = *(const float2*)(g_X + (2ull * TBROWS
                          + (size_t)t * B_SZ) * DH + mE * DH + nBe);
        grid_barrier(lgen);

        // ======================= PHASE B (candidate + update) =============
        float2 uvB = *(const float2*)(g_u + mE * DH + nBe);

        float accB[4][4];
#pragma unroll
        for (int mf = 0; mf < 4; mf++)
#pragma unroll
            for (int e = 0; e < 4; e++) accB[mf][e] = 0.f;

        stage_slice(my_stg, g_rhh, g_rhl, kw);
        CP_COMMIT();

#pragma unroll
        for (int j = 0; j < 8; j++) {
            if (j < 7) {
                stage_slice(my_stg + ((j + 1) & 1) * STG_STAGE, g_rhh, g_rhl,
                            kw + 16 * (j + 1));
                CP_COMMIT();
                CP_WAIT(1);
            } else {
                CP_WAIT(0);
            }
            __syncwarp();

            const int kt = 4 * wid + (j >> 1);
            const int s  = j & 1;
            uint32_t bB = sm0 + SM_WSB + kt * 640
                        + (lane & 7) * 80 + (lane >> 3) * 16;
            uint32_t r0, r1, r2, r3;
            uint32_t bh[2], bl[2];
            LDSM_X4(r0, r1, r2, r3, bB);
            if (s == 0) { bh[0] = r0; bh[1] = r1; } else { bh[0] = r2; bh[1] = r3; }
            LDSM_X4(r0, r1, r2, r3, bB + WSB_HALF);
            if (s == 0) { bl[0] = r0; bl[1] = r1; } else { bl[0] = r2; bl[1] = r3; }
            const uint32_t ab = my_stg + (j & 1) * STG_STAGE;
#pragma unroll
            for (int mf = 0; mf < 4; mf++) {
                uint32_t ra = ab + (mf * 16 + (lane & 15)) * 48 + (lane >> 4) * 16;
                uint32_t ah[4], al[4];
                LDSM_X4(ah[0], ah[1], ah[2], ah[3], ra);
                LDSM_X4(al[0], al[1], al[2], al[3], ra + 3072);
                MMA_BF16(accB[mf], ah, bh);
                MMA_BF16(accB[mf], ah, bl);
                MMA_BF16(accB[mf], al, bh);
            }
        }

        // ---- reduction + state update epilogue
        {
            float* rw = red + wid * 3072;
#pragma unroll
            for (int mf = 0; mf < 4; mf++) {
                int row = mf * 16 + (lane >> 2);
                int col = (lane & 3) * 2;
                *(float2*)&rw[row * 10 + col] =
                    make_float2(accB[mf][0], accB[mf][1]);
                *(float2*)&rw[(row + 8) * 10 + col] =
                    make_float2(accB[mf][2], accB[mf][3]);
            }
        }
        __syncthreads();
        {
            float2 sv = make_float2(0.f, 0.f);
#pragma unroll
            for (int w = 0; w < 8; w++) {
                float2 v = *(float2*)&red[w * 3072 + mE * 10 + cbB];
                sv.x += v.x; sv.y += v.y;
            }
            float c0 = tanhf(sv.x + xcB.x);
            float c1 = tanhf(sv.y + xcB.y);
            float hn0 = (1.f - uvB.x) * hcar0 + uvB.x * c0;
            float hn1 = (1.f - uvB.y) * hcar1 + uvB.y * c1;
            hcar0 = hn0; hcar1 = hn1;
            *(float2*)&g_h[mE * DH + nBe] = make_float2(hn0, hn1);
            __nv_bfloat162 hh2, hl2;
            hh2.x = __float2bfloat16(hn0); hh2.y = __float2bfloat16(hn1);
            hl2.x = __float2bfloat16(hn0 - __bfloat162float(hh2.x));
            hl2.y = __float2bfloat16(hn1 - __bfloat162float(hh2.y));
            *(__nv_bfloat162*)&g_hh[mE * DH + nBe] = hh2;
            *(__nv_bfloat162*)&g_hl[mE * DH + nBe] = hl2;
            size_t ob = ((size_t)t * B_SZ + mE) * DH + nBe;
            *(float2*)&out[ob] = make_float2(hn0, hn1);
            if (write_tail && t == T_STEPS - 1) {
                size_t tb = ((size_t)T_STEPS * B_SZ + mE) * DH + nBe;
                *(float2*)&out[tb] = make_float2(hn0, hn1);
            }
        }
        // prefetch next step's phase-A X (depends only on t+1) BEFORE barrier
        if (t + 1 < T_STEPS) {
            xgA = *(const float4*)(g_X + ((size_t)gA * TBROWS
                      + (size_t)(t + 1) * B_SZ) * DH + mE * DH + nAe);
        }
        grid_barrier(lgen);
    }
}

// ============================================================================
// Launch: exactly 3 kernels per call
// ============================================================================
extern "C" void kernel_launch(void* const* d_in, const int* in_sizes, int n_in,
                              void* d_out, int out_size) {
    const float* emb    = (const float*)d_in[0];
    const float* hx     = (const float*)d_in[1];
    const float* w_ih_u = (const float*)d_in[2];
    const float* w_ih_r = (const float*)d_in[3];
    const float* w_ih_c = (const float*)d_in[4];
    const float* w_hh_u = (const float*)d_in[5];
    const float* w_hh_r = (const float*)d_in[6];
    const float* w_hh_c = (const float*)d_in[7];
    const float* b_u    = (const float*)d_in[8];
    const float* b_r    = (const float*)d_in[9];
    const float* b_c    = (const float*)d_in[10];
    float* out = (float*)d_out;

    const long long main_elems = (long long)T_STEPS * B_SZ * DH;
    int write_tail = ((long long)out_size >= main_elems + (long long)B_SZ * DH) ? 1 : 0;

    cudaFuncSetAttribute(gemm_input_tc,
                         cudaFuncAttributeMaxDynamicSharedMemorySize, GEMM_SM);
    cudaFuncSetAttribute(gru_pers_tc,
                         cudaFuncAttributeMaxDynamicSharedMemorySize, PERS_SM);

    int prep_blocks = (int)((PREP_TOT + 255) / 256);
    prep_all<<<prep_blocks, 256>>>(emb, w_ih_u, w_ih_r, w_ih_c, hx);

    dim3 g1(DH / 128, TBROWS / 128, 3);
    gemm_input_tc<<<g1, 256, GEMM_SM>>>(b_u, b_r, b_c);
    gru_pers_tc<<<NBLK, NTHR, PERS_SM>>>(w_hh_u, w_hh_r, w_hh_c, out, write_tail);
}